// round 1
// baseline (speedup 1.0000x reference)
#include <cuda_runtime.h>
#include <math.h>

#define D_MODEL 1024
#define NHEADS  16
#define HDIM    64
#define BATCH   2
#define SEQ     2048
#define MTOT    (BATCH*SEQ)          // 4096

// Scratch (allocation-free rule: static __device__ globals)
__device__ float g_q[BATCH*NHEADS*SEQ*HDIM];
__device__ float g_k[BATCH*NHEADS*SEQ*HDIM];
__device__ float g_v[BATCH*NHEADS*SEQ*HDIM];
__device__ float g_att[MTOT*D_MODEL];

// ---------------------------------------------------------------------------
// SGEMM (NT): C[m,n] = sum_k A[m,k] * W[n,k]
// A: [M,K] row-major, W: [N,K] row-major. 128x128 tile, BK=8, 256 thr, 8x8/thr.
// MODE 0: scatter into [B, H, S, d] head-wise layout. MODE 1: row-major [M,N].
// ---------------------------------------------------------------------------
template<int MODE>
__global__ void __launch_bounds__(256) sgemm_nt(const float* __restrict__ A,
                                                const float* __restrict__ W,
                                                float* __restrict__ C,
                                                int M, int N, int K)
{
    __shared__ float As[8][128];
    __shared__ float Bs[8][128];

    const int tid  = threadIdx.x;
    const int brow = blockIdx.y;
    const int bcol = blockIdx.x;

    const int lr = tid >> 1;          // 0..127
    const int lc = (tid & 1) * 4;     // 0 or 4

    const float* Aptr = A + (size_t)(brow*128 + lr)*K + lc;
    const float* Wptr = W + (size_t)(bcol*128 + lr)*K + lc;

    const int tx = tid & 15;
    const int ty = tid >> 4;

    float acc[8][8];
    #pragma unroll
    for (int i = 0; i < 8; i++)
        #pragma unroll
        for (int j = 0; j < 8; j++) acc[i][j] = 0.0f;

    for (int kk = 0; kk < K; kk += 8) {
        float4 av = *(const float4*)(Aptr + kk);
        float4 bv = *(const float4*)(Wptr + kk);
        __syncthreads();
        As[lc+0][lr] = av.x; As[lc+1][lr] = av.y;
        As[lc+2][lr] = av.z; As[lc+3][lr] = av.w;
        Bs[lc+0][lr] = bv.x; Bs[lc+1][lr] = bv.y;
        Bs[lc+2][lr] = bv.z; Bs[lc+3][lr] = bv.w;
        __syncthreads();

        #pragma unroll
        for (int k = 0; k < 8; k++) {
            float ar[8], br[8];
            *(float4*)&ar[0] = *(const float4*)&As[k][ty*8];
            *(float4*)&ar[4] = *(const float4*)&As[k][ty*8+4];
            *(float4*)&br[0] = *(const float4*)&Bs[k][tx*8];
            *(float4*)&br[4] = *(const float4*)&Bs[k][tx*8+4];
            #pragma unroll
            for (int i = 0; i < 8; i++)
                #pragma unroll
                for (int j = 0; j < 8; j++)
                    acc[i][j] = fmaf(ar[i], br[j], acc[i][j]);
        }
    }

    const int row0 = brow*128 + ty*8;
    const int col0 = bcol*128 + tx*8;

    if (MODE == 1) {
        #pragma unroll
        for (int i = 0; i < 8; i++) {
            float4 v0 = make_float4(acc[i][0], acc[i][1], acc[i][2], acc[i][3]);
            float4 v1 = make_float4(acc[i][4], acc[i][5], acc[i][6], acc[i][7]);
            *(float4*)(C + (size_t)(row0+i)*N + col0)     = v0;
            *(float4*)(C + (size_t)(row0+i)*N + col0 + 4) = v1;
        }
    } else {
        // scatter to [B, H, S, d]; an 8-wide column block never crosses a head
        const int h  = col0 >> 6;
        const int dd = col0 & 63;
        #pragma unroll
        for (int i = 0; i < 8; i++) {
            const int row = row0 + i;
            const int b   = row >> 11;         // /SEQ
            const int s   = row & (SEQ-1);
            float* dst = C + ((size_t)(b*NHEADS + h)*SEQ + s)*HDIM + dd;
            float4 v0 = make_float4(acc[i][0], acc[i][1], acc[i][2], acc[i][3]);
            float4 v1 = make_float4(acc[i][4], acc[i][5], acc[i][6], acc[i][7]);
            *(float4*)(dst)     = v0;
            *(float4*)(dst + 4) = v1;
        }
    }
}

// ---------------------------------------------------------------------------
// RoPE in-place on q and k in [B, H, S, d] layout (interleaved even/odd pairs)
// ---------------------------------------------------------------------------
__global__ void rope_kernel(float* __restrict__ q, float* __restrict__ k)
{
    const int total = BATCH*NHEADS*SEQ*(HDIM/2);
    int i = blockIdx.x*blockDim.x + threadIdx.x;
    if (i >= total) return;

    const int t = i & 31;                  // pair index within head_dim
    const int s = (i >> 5) & (SEQ - 1);    // sequence position
    const size_t base = (size_t)(i >> 5) * HDIM + 2*t;   // (bh*S+s)*64 + 2t

    // inv_freq = 10000^(-2t/64); log2(10000) = 13.287712379549449
    const float ang = (float)s * exp2f((float)t * (-2.0f/(float)HDIM) * 13.28771237954945f);
    float sn, cs;
    sincosf(ang, &sn, &cs);

    float2 qv = *(float2*)(q + base);
    float2 kv = *(float2*)(k + base);
    float2 qo, ko;
    qo.x = qv.x*cs - qv.y*sn;  qo.y = qv.x*sn + qv.y*cs;
    ko.x = kv.x*cs - kv.y*sn;  ko.y = kv.x*sn + kv.y*cs;
    *(float2*)(q + base) = qo;
    *(float2*)(k + base) = ko;
}

// ---------------------------------------------------------------------------
// Flash attention (causal), fp32. 64x64 tiles, 256 thr, per-thread 4x4.
// Row mapping: i = ty*4 + r. Column mapping: j = tx + 16*c (conflict-friendly).
// Output written back to [B, S, D_MODEL] for the final projection.
// ---------------------------------------------------------------------------
#define FPAD 68

__global__ void __launch_bounds__(256) flash_kernel(const float* __restrict__ gq,
                                                    const float* __restrict__ gk,
                                                    const float* __restrict__ gv,
                                                    float* __restrict__ out)
{
    extern __shared__ float sm[];
    float* Qs = sm;                   // [64][68]
    float* Ks = sm + 64*FPAD;         // [64][68]
    float* Vs = sm + 2*64*FPAD;       // [64][68]
    float* Ps = sm + 3*64*FPAD;       // [64][68]

    const int tid = threadIdx.x;
    const int tx  = tid & 15;
    const int ty  = tid >> 4;
    const int qt  = blockIdx.x;
    const int h   = blockIdx.y;
    const int b   = blockIdx.z;

    const float* Qg = gq + ((size_t)(b*NHEADS + h)*SEQ + qt*64)*HDIM;
    const float* Kg = gk + ((size_t)(b*NHEADS + h)*SEQ)*HDIM;
    const float* Vg = gv + ((size_t)(b*NHEADS + h)*SEQ)*HDIM;

    // loader mapping: row = tid/4 (0..63), col base = (tid%4)*16, 4x float4
    const int ldr = tid >> 2;
    const int ldc = (tid & 3) * 16;

    // load Q tile (pre-scaled by 1/sqrt(64) = 0.125)
    #pragma unroll
    for (int u = 0; u < 4; u++) {
        float4 v = *(const float4*)(Qg + (size_t)ldr*HDIM + ldc + 4*u);
        v.x *= 0.125f; v.y *= 0.125f; v.z *= 0.125f; v.w *= 0.125f;
        *(float4*)&Qs[ldr*FPAD + ldc + 4*u] = v;
    }

    float o[4][4];
    float m[4], l[4];
    #pragma unroll
    for (int r = 0; r < 4; r++) {
        m[r] = -INFINITY; l[r] = 0.0f;
        #pragma unroll
        for (int c = 0; c < 4; c++) o[r][c] = 0.0f;
    }

    const int i0 = ty*4;                 // local q-row base for this thread

    for (int kt = 0; kt <= qt; kt++) {
        __syncthreads();   // prior O-gemm done reading Vs/Ps
        {
            const float* kg = Kg + ((size_t)(kt*64 + ldr))*HDIM + ldc;
            const float* vg = Vg + ((size_t)(kt*64 + ldr))*HDIM + ldc;
            #pragma unroll
            for (int u = 0; u < 4; u++) {
                *(float4*)&Ks[ldr*FPAD + ldc + 4*u] = *(const float4*)(kg + 4*u);
                *(float4*)&Vs[ldr*FPAD + ldc + 4*u] = *(const float4*)(vg + 4*u);
            }
        }
        __syncthreads();

        // S = Q K^T (scaled already)
        float s[4][4];
        #pragma unroll
        for (int r = 0; r < 4; r++)
            #pragma unroll
            for (int c = 0; c < 4; c++) s[r][c] = 0.0f;

        #pragma unroll
        for (int d4 = 0; d4 < 16; d4++) {
            float4 qv[4], kv[4];
            #pragma unroll
            for (int r = 0; r < 4; r++)
                qv[r] = *(const float4*)&Qs[(i0+r)*FPAD + d4*4];
            #pragma unroll
            for (int c = 0; c < 4; c++)
                kv[c] = *(const float4*)&Ks[(tx + 16*c)*FPAD + d4*4];
            #pragma unroll
            for (int r = 0; r < 4; r++)
                #pragma unroll
                for (int c = 0; c < 4; c++) {
                    s[r][c] = fmaf(qv[r].x, kv[c].x, s[r][c]);
                    s[r][c] = fmaf(qv[r].y, kv[c].y, s[r][c]);
                    s[r][c] = fmaf(qv[r].z, kv[c].z, s[r][c]);
                    s[r][c] = fmaf(qv[r].w, kv[c].w, s[r][c]);
                }
        }

        // causal mask (only the diagonal tile needs it)
        if (kt == qt) {
            #pragma unroll
            for (int r = 0; r < 4; r++) {
                const int irow = i0 + r;               // local == global offset same tile
                #pragma unroll
                for (int c = 0; c < 4; c++)
                    if (tx + 16*c > irow) s[r][c] = -INFINITY;
            }
        }

        // online softmax
        #pragma unroll
        for (int r = 0; r < 4; r++) {
            float mx = fmaxf(fmaxf(s[r][0], s[r][1]), fmaxf(s[r][2], s[r][3]));
            #pragma unroll
            for (int off = 8; off >= 1; off >>= 1)
                mx = fmaxf(mx, __shfl_xor_sync(0xffffffffu, mx, off));
            const float mn    = fmaxf(m[r], mx);
            const float alpha = __expf(m[r] - mn);
            m[r] = mn;
            float sum = 0.0f;
            #pragma unroll
            for (int c = 0; c < 4; c++) {
                float p = __expf(s[r][c] - mn);
                s[r][c] = p;
                sum += p;
            }
            #pragma unroll
            for (int off = 8; off >= 1; off >>= 1)
                sum += __shfl_xor_sync(0xffffffffu, sum, off);
            l[r] = l[r]*alpha + sum;
            #pragma unroll
            for (int c = 0; c < 4; c++) o[r][c] *= alpha;
        }

        // stage P to smem
        #pragma unroll
        for (int r = 0; r < 4; r++)
            #pragma unroll
            for (int c = 0; c < 4; c++)
                Ps[(i0+r)*FPAD + tx + 16*c] = s[r][c];
        __syncthreads();

        // O += P V
        #pragma unroll
        for (int j4 = 0; j4 < 16; j4++) {
            float4 pv[4];
            #pragma unroll
            for (int r = 0; r < 4; r++)
                pv[r] = *(const float4*)&Ps[(i0+r)*FPAD + j4*4];
            #pragma unroll
            for (int jj = 0; jj < 4; jj++) {
                float vv[4];
                #pragma unroll
                for (int c = 0; c < 4; c++)
                    vv[c] = Vs[(j4*4+jj)*FPAD + tx + 16*c];
                #pragma unroll
                for (int r = 0; r < 4; r++) {
                    const float pe = (jj == 0) ? pv[r].x : (jj == 1) ? pv[r].y :
                                     (jj == 2) ? pv[r].z : pv[r].w;
                    #pragma unroll
                    for (int c = 0; c < 4; c++)
                        o[r][c] = fmaf(pe, vv[c], o[r][c]);
                }
            }
        }
    }

    // normalize + write back to [B, S, D_MODEL]
    #pragma unroll
    for (int r = 0; r < 4; r++) {
        const float inv = 1.0f / l[r];
        const int srow  = qt*64 + i0 + r;
        float* dst = out + ((size_t)b*SEQ + srow)*D_MODEL + h*HDIM + tx;
        #pragma unroll
        for (int c = 0; c < 4; c++)
            dst[16*c] = o[r][c] * inv;
    }
}

// ---------------------------------------------------------------------------
extern "C" void kernel_launch(void* const* d_in, const int* in_sizes, int n_in,
                              void* d_out, int out_size)
{
    (void)in_sizes; (void)n_in; (void)out_size;
    const float* x  = (const float*)d_in[0];
    const float* Wq = (const float*)d_in[1];
    const float* Wk = (const float*)d_in[2];
    const float* Wv = (const float*)d_in[3];
    const float* Wo = (const float*)d_in[4];
    float* out = (float*)d_out;

    float *q, *k, *v, *att;
    cudaGetSymbolAddress((void**)&q,   g_q);
    cudaGetSymbolAddress((void**)&k,   g_k);
    cudaGetSymbolAddress((void**)&v,   g_v);
    cudaGetSymbolAddress((void**)&att, g_att);

    dim3 ggrid(D_MODEL/128, MTOT/128);   // (8, 32)

    // QKV projections -> [B, H, S, d]
    sgemm_nt<0><<<ggrid, 256>>>(x, Wq, q, MTOT, D_MODEL, D_MODEL);
    sgemm_nt<0><<<ggrid, 256>>>(x, Wk, k, MTOT, D_MODEL, D_MODEL);
    sgemm_nt<0><<<ggrid, 256>>>(x, Wv, v, MTOT, D_MODEL, D_MODEL);

    // RoPE on q, k
    const int pairs = BATCH*NHEADS*SEQ*(HDIM/2);
    rope_kernel<<<(pairs + 255)/256, 256>>>(q, k);

    // Causal flash attention -> [B, S, D_MODEL]
    const int shmem = 4 * 64 * FPAD * (int)sizeof(float);   // 69632 B
    cudaFuncSetAttribute(flash_kernel, cudaFuncAttributeMaxDynamicSharedMemorySize, shmem);
    flash_kernel<<<dim3(SEQ/64, NHEADS, BATCH), 256, shmem>>>(q, k, v, att);

    // Output projection
    sgemm_nt<1><<<ggrid, 256>>>(att, Wo, out, MTOT, D_MODEL, D_MODEL);
}

// round 4
// speedup vs baseline: 1.5458x; 1.5458x over previous
#include <cuda_runtime.h>
#include <cuda_bf16.h>
#include <math.h>
#include <stdint.h>

#define D_MODEL 1024
#define NHEADS  16
#define HDIM    64
#define BATCH   2
#define SEQ     2048
#define MTOT    (BATCH*SEQ)          // 4096
#define GK      1024

// Scratch (allocation-free rule: static __device__ globals)
__device__ float g_q[MTOT*D_MODEL];
__device__ float g_k[MTOT*D_MODEL];
__device__ float g_v[MTOT*D_MODEL];
__device__ float g_att[MTOT*D_MODEL];

// ===========================================================================
// helpers
// ===========================================================================
__device__ __forceinline__ uint32_t smem_u32(const void* p) {
    uint32_t a;
    asm("{ .reg .u64 t; cvta.to.shared.u64 t, %1; cvt.u32.u64 %0, t; }" : "=r"(a) : "l"(p));
    return a;
}

__device__ __forceinline__ void ldsm_x4(uint32_t* r, uint32_t addr) {
    asm volatile("ldmatrix.sync.aligned.m8n8.x4.shared.b16 {%0,%1,%2,%3}, [%4];"
        : "=r"(r[0]), "=r"(r[1]), "=r"(r[2]), "=r"(r[3]) : "r"(addr));
}

__device__ __forceinline__ void mma_bf16(float* c, const uint32_t* a, uint32_t b0, uint32_t b1) {
    asm volatile("mma.sync.aligned.m16n8k16.row.col.f32.bf16.bf16.f32 "
        "{%0,%1,%2,%3}, {%4,%5,%6,%7}, {%8,%9}, {%0,%1,%2,%3};"
        : "+f"(c[0]), "+f"(c[1]), "+f"(c[2]), "+f"(c[3])
        : "r"(a[0]), "r"(a[1]), "r"(a[2]), "r"(a[3]), "r"(b0), "r"(b1));
}

// swizzled byte offset inside a [128 rows][32 bf16] tile (64B rows, 4x16B chunks)
// chunk' = chunk ^ ((row>>1)&3)  -> conflict-free ldmatrix phases + stores
__device__ __forceinline__ uint32_t sw_off(int row, int chunk) {
    return (uint32_t)(row*64 + ((chunk ^ ((row>>1)&3))<<4));
}

// split 8 fp32 -> 8 bf16 hi + 8 bf16 lo, packed as uint4 each
__device__ __forceinline__ void split8(const float* f, uint4& h4, uint4& l4) {
    uint32_t hw[4], lw[4];
    #pragma unroll
    for (int j = 0; j < 4; j++) {
        float x = f[2*j], y = f[2*j+1];
        __nv_bfloat162 hh = __floats2bfloat162_rn(x, y);
        float hx = __bfloat162float(hh.x), hy = __bfloat162float(hh.y);
        __nv_bfloat162 ll = __floats2bfloat162_rn(x - hx, y - hy);
        hw[j] = *(uint32_t*)&hh;
        lw[j] = *(uint32_t*)&ll;
    }
    h4 = make_uint4(hw[0], hw[1], hw[2], hw[3]);
    l4 = make_uint4(lw[0], lw[1], lw[2], lw[3]);
}

// ===========================================================================
// bf16x3 mma.sync GEMM (NT): C[m,n] = sum_k A[m,k]*W[n,k], fp32 in/out.
// 128x128 tile, BK=32, 256 thr (8 warps, 2x4), warp tile 64x32.
// D += Ah*Bh + Al*Bh + Ah*Bl  (error ~1e-5 rel, fp32-faithful vs 1e-3 gate).
// ===========================================================================
#define BKK       32
#define NCHUNK    (GK/BKK)           // 32
#define TILE_B16  (128*32*2)         // 8192 bytes per bf16 tile
#define STAGE_B   (4*TILE_B16)       // Ah, Al, Bh, Bl = 32768
#define GSMEM     (2*STAGE_B)        // 65536 (double buffer)

__global__ void __launch_bounds__(256) gemm_bf16x3(const float* __restrict__ A,
                                                   const float* __restrict__ W,
                                                   float* __restrict__ C)
{
    extern __shared__ char sm[];
    const int tid  = threadIdx.x;
    const int wid  = tid >> 5;
    const int lane = tid & 31;
    const int brow = blockIdx.y;
    const int bcol = blockIdx.x;

    const int wm = wid >> 2;          // 0..1 (m half)
    const int wn = wid & 3;           // 0..3 (n quarter)

    // loader mapping: row = tid>>1 (0..127), half = tid&1 (k 0-15 / 16-31)
    const int lrow = tid >> 1;
    const int lhalf = tid & 1;
    const float* Ag = A + (size_t)(brow*128 + lrow)*GK + lhalf*16;
    const float* Bg = W + (size_t)(bcol*128 + lrow)*GK + lhalf*16;
    const uint32_t so0 = sw_off(lrow, lhalf*2);
    const uint32_t so1 = sw_off(lrow, lhalf*2 + 1);

    // ldmatrix lane decomposition
    const int l15 = lane & 15;
    const int l16 = lane >> 4;

    float acc[4][4][4];
    #pragma unroll
    for (int i = 0; i < 4; i++)
        #pragma unroll
        for (int j = 0; j < 4; j++)
            #pragma unroll
            for (int e = 0; e < 4; e++) acc[i][j][e] = 0.0f;

    // prologue: prefetch chunk 0
    float4 pa[4], pb[4];
    #pragma unroll
    for (int u = 0; u < 4; u++) {
        pa[u] = *(const float4*)(Ag + 4*u);
        pb[u] = *(const float4*)(Bg + 4*u);
    }

    for (int ch = 0; ch < NCHUNK; ch++) {
        char* stg = sm + (ch & 1)*STAGE_B;
        char* sAh = stg;
        char* sAl = stg + TILE_B16;
        char* sBh = stg + 2*TILE_B16;
        char* sBl = stg + 3*TILE_B16;

        // split + store prefetched chunk
        {
            uint4 h4, l4;
            split8(&pa[0].x, h4, l4);
            *(uint4*)(sAh + so0) = h4; *(uint4*)(sAl + so0) = l4;
            split8(&pa[2].x, h4, l4);
            *(uint4*)(sAh + so1) = h4; *(uint4*)(sAl + so1) = l4;
            split8(&pb[0].x, h4, l4);
            *(uint4*)(sBh + so0) = h4; *(uint4*)(sBl + so0) = l4;
            split8(&pb[2].x, h4, l4);
            *(uint4*)(sBh + so1) = h4; *(uint4*)(sBl + so1) = l4;
        }
        __syncthreads();

        // prefetch next chunk (LDG latency overlaps mma below)
        if (ch + 1 < NCHUNK) {
            #pragma unroll
            for (int u = 0; u < 4; u++) {
                pa[u] = *(const float4*)(Ag + (ch+1)*BKK + 4*u);
                pb[u] = *(const float4*)(Bg + (ch+1)*BKK + 4*u);
            }
        }

        const uint32_t uAh = smem_u32(sAh), uAl = smem_u32(sAl);
        const uint32_t uBh = smem_u32(sBh), uBl = smem_u32(sBl);

        // two k16 steps
        #pragma unroll
        for (int s = 0; s < 2; s++) {
            const int chunk = s*2 + l16;

            // B fragments: 2 groups of n16 (covering 4 n8 tiles), hi+lo
            uint32_t bh[2][4], bl[2][4];
            #pragma unroll
            for (int ng = 0; ng < 2; ng++) {
                const int brow_l = wn*32 + ng*16 + l15;
                const uint32_t off = sw_off(brow_l, chunk);
                ldsm_x4(bh[ng], uBh + off);
                ldsm_x4(bl[ng], uBl + off);
            }

            #pragma unroll
            for (int mt = 0; mt < 4; mt++) {
                const int arow_l = wm*64 + mt*16 + l15;
                const uint32_t off = sw_off(arow_l, chunk);
                uint32_t ah[4], al[4];
                ldsm_x4(ah, uAh + off);
                ldsm_x4(al, uAl + off);

                #pragma unroll
                for (int nt = 0; nt < 4; nt++) {
                    const int ng = nt >> 1, ix = nt & 1;
                    const uint32_t b0h = bh[ng][ix], b1h = bh[ng][2+ix];
                    const uint32_t b0l = bl[ng][ix], b1l = bl[ng][2+ix];
                    mma_bf16(acc[mt][nt], ah, b0h, b1h);
                    mma_bf16(acc[mt][nt], al, b0h, b1h);
                    mma_bf16(acc[mt][nt], ah, b0l, b1l);
                }
            }
        }
        __syncthreads();
    }

    // epilogue: c-frag layout m16n8: c0,c1 -> (row l>>2, col (l&3)*2), c2,c3 -> row+8
    const int rbase = brow*128 + wm*64 + (lane >> 2);
    const int cbase = bcol*128 + wn*32 + (lane & 3)*2;
    #pragma unroll
    for (int mt = 0; mt < 4; mt++) {
        #pragma unroll
        for (int nt = 0; nt < 4; nt++) {
            float* p = C + (size_t)(rbase + mt*16)*D_MODEL + cbase + nt*8;
            *(float2*)p = make_float2(acc[mt][nt][0], acc[mt][nt][1]);
            *(float2*)(p + 8*D_MODEL) = make_float2(acc[mt][nt][2], acc[mt][nt][3]);
        }
    }
}

// ---------------------------------------------------------------------------
// RoPE in-place on q and k in [B, S, H, d] layout (interleaved pairs).
// ---------------------------------------------------------------------------
__global__ void rope_kernel(float* __restrict__ q, float* __restrict__ k)
{
    const int total = MTOT*D_MODEL/2;
    int i = blockIdx.x*blockDim.x + threadIdx.x;
    if (i >= total) return;

    const int t = i & 31;                  // pair index within head_dim
    const int s = (i >> 9) & (SEQ - 1);    // sequence position ([b][s][h][32 pairs])
    const size_t base = (size_t)i * 2;

    const float ang = (float)s * exp2f((float)t * (-2.0f/(float)HDIM) * 13.28771237954945f);
    float sn, cs;
    sincosf(ang, &sn, &cs);

    float2 qv = *(float2*)(q + base);
    float2 kv = *(float2*)(k + base);
    float2 qo, ko;
    qo.x = qv.x*cs - qv.y*sn;  qo.y = qv.x*sn + qv.y*cs;
    ko.x = kv.x*cs - kv.y*sn;  ko.y = kv.x*sn + kv.y*cs;
    *(float2*)(q + base) = qo;
    *(float2*)(k + base) = ko;
}

// ---------------------------------------------------------------------------
// Flash attention (causal), fp32. 64x64 tiles, 256 thr, per-thread 4x4.
// Q/K/V in [B, S, H, d] (row stride D_MODEL). Output [B, S, D_MODEL].
// ---------------------------------------------------------------------------
#define FPAD 68

__global__ void __launch_bounds__(256) flash_kernel(const float* __restrict__ gq,
                                                    const float* __restrict__ gk,
                                                    const float* __restrict__ gv,
                                                    float* __restrict__ out)
{
    extern __shared__ float smf[];
    float* Qs = smf;                   // [64][68]
    float* Ks = smf + 64*FPAD;
    float* Vs = smf + 2*64*FPAD;
    float* Ps = smf + 3*64*FPAD;

    const int tid = threadIdx.x;
    const int tx  = tid & 15;
    const int ty  = tid >> 4;
    const int qt  = blockIdx.x;
    const int h   = blockIdx.y;
    const int b   = blockIdx.z;

    const float* Qg = gq + ((size_t)(b*SEQ + qt*64))*D_MODEL + h*HDIM;
    const float* Kg = gk + ((size_t)(b*SEQ))*D_MODEL + h*HDIM;
    const float* Vg = gv + ((size_t)(b*SEQ))*D_MODEL + h*HDIM;

    const int ldr = tid >> 2;          // row 0..63
    const int ldc = (tid & 3) * 16;    // col base

    #pragma unroll
    for (int u = 0; u < 4; u++) {
        float4 v = *(const float4*)(Qg + (size_t)ldr*D_MODEL + ldc + 4*u);
        v.x *= 0.125f; v.y *= 0.125f; v.z *= 0.125f; v.w *= 0.125f;
        *(float4*)&Qs[ldr*FPAD + ldc + 4*u] = v;
    }

    float o[4][4];
    float m[4], l[4];
    #pragma unroll
    for (int r = 0; r < 4; r++) {
        m[r] = -INFINITY; l[r] = 0.0f;
        #pragma unroll
        for (int c = 0; c < 4; c++) o[r][c] = 0.0f;
    }

    const int i0 = ty*4;

    for (int kt = 0; kt <= qt; kt++) {
        __syncthreads();
        {
            const float* kg = Kg + ((size_t)(kt*64 + ldr))*D_MODEL + ldc;
            const float* vg = Vg + ((size_t)(kt*64 + ldr))*D_MODEL + ldc;
            #pragma unroll
            for (int u = 0; u < 4; u++) {
                *(float4*)&Ks[ldr*FPAD + ldc + 4*u] = *(const float4*)(kg + 4*u);
                *(float4*)&Vs[ldr*FPAD + ldc + 4*u] = *(const float4*)(vg + 4*u);
            }
        }
        __syncthreads();

        float s[4][4];
        #pragma unroll
        for (int r = 0; r < 4; r++)
            #pragma unroll
            for (int c = 0; c < 4; c++) s[r][c] = 0.0f;

        #pragma unroll
        for (int d4 = 0; d4 < 16; d4++) {
            float4 qv[4], kv[4];
            #pragma unroll
            for (int r = 0; r < 4; r++)
                qv[r] = *(const float4*)&Qs[(i0+r)*FPAD + d4*4];
            #pragma unroll
            for (int c = 0; c < 4; c++)
                kv[c] = *(const float4*)&Ks[(tx + 16*c)*FPAD + d4*4];
            #pragma unroll
            for (int r = 0; r < 4; r++)
                #pragma unroll
                for (int c = 0; c < 4; c++) {
                    s[r][c] = fmaf(qv[r].x, kv[c].x, s[r][c]);
                    s[r][c] = fmaf(qv[r].y, kv[c].y, s[r][c]);
                    s[r][c] = fmaf(qv[r].z, kv[c].z, s[r][c]);
                    s[r][c] = fmaf(qv[r].w, kv[c].w, s[r][c]);
                }
        }

        if (kt == qt) {
            #pragma unroll
            for (int r = 0; r < 4; r++) {
                const int irow = i0 + r;
                #pragma unroll
                for (int c = 0; c < 4; c++)
                    if (tx + 16*c > irow) s[r][c] = -INFINITY;
            }
        }

        #pragma unroll
        for (int r = 0; r < 4; r++) {
            float mx = fmaxf(fmaxf(s[r][0], s[r][1]), fmaxf(s[r][2], s[r][3]));
            #pragma unroll
            for (int off = 8; off >= 1; off >>= 1)
                mx = fmaxf(mx, __shfl_xor_sync(0xffffffffu, mx, off));
            const float mn    = fmaxf(m[r], mx);
            const float alpha = __expf(m[r] - mn);
            m[r] = mn;
            float sum = 0.0f;
            #pragma unroll
            for (int c = 0; c < 4; c++) {
                float p = __expf(s[r][c] - mn);
                s[r][c] = p;
                sum += p;
            }
            #pragma unroll
            for (int off = 8; off >= 1; off >>= 1)
                sum += __shfl_xor_sync(0xffffffffu, sum, off);
            l[r] = l[r]*alpha + sum;
            #pragma unroll
            for (int c = 0; c < 4; c++) o[r][c] *= alpha;
        }

        #pragma unroll
        for (int r = 0; r < 4; r++)
            #pragma unroll
            for (int c = 0; c < 4; c++)
                Ps[(i0+r)*FPAD + tx + 16*c] = s[r][c];
        __syncthreads();

        #pragma unroll
        for (int j4 = 0; j4 < 16; j4++) {
            float4 pv[4];
            #pragma unroll
            for (int r = 0; r < 4; r++)
                pv[r] = *(const float4*)&Ps[(i0+r)*FPAD + j4*4];
            #pragma unroll
            for (int jj = 0; jj < 4; jj++) {
                float vv[4];
                #pragma unroll
                for (int c = 0; c < 4; c++)
                    vv[c] = Vs[(j4*4+jj)*FPAD + tx + 16*c];
                #pragma unroll
                for (int r = 0; r < 4; r++) {
                    const float pe = (jj == 0) ? pv[r].x : (jj == 1) ? pv[r].y :
                                     (jj == 2) ? pv[r].z : pv[r].w;
                    #pragma unroll
                    for (int c = 0; c < 4; c++)
                        o[r][c] = fmaf(pe, vv[c], o[r][c]);
                }
            }
        }
    }

    #pragma unroll
    for (int r = 0; r < 4; r++) {
        const float inv = 1.0f / l[r];
        const int srow  = qt*64 + i0 + r;
        float* dst = out + ((size_t)b*SEQ + srow)*D_MODEL + h*HDIM + tx;
        #pragma unroll
        for (int c = 0; c < 4; c++)
            dst[16*c] = o[r][c] * inv;
    }
}

// ---------------------------------------------------------------------------
extern "C" void kernel_launch(void* const* d_in, const int* in_sizes, int n_in,
                              void* d_out, int out_size)
{
    (void)in_sizes; (void)n_in; (void)out_size;
    const float* x  = (const float*)d_in[0];
    const float* Wq = (const float*)d_in[1];
    const float* Wk = (const float*)d_in[2];
    const float* Wv = (const float*)d_in[3];
    const float* Wo = (const float*)d_in[4];
    float* out = (float*)d_out;

    float *q, *k, *v, *att;
    cudaGetSymbolAddress((void**)&q,   g_q);
    cudaGetSymbolAddress((void**)&k,   g_k);
    cudaGetSymbolAddress((void**)&v,   g_v);
    cudaGetSymbolAddress((void**)&att, g_att);

    cudaFuncSetAttribute(gemm_bf16x3, cudaFuncAttributeMaxDynamicSharedMemorySize, GSMEM);

    dim3 ggrid(D_MODEL/128, MTOT/128);   // (8, 32) = 256 CTAs

    // QKV projections -> [B, S, H, d] (row-major [MTOT, D_MODEL])
    gemm_bf16x3<<<ggrid, 256, GSMEM>>>(x, Wq, q);
    gemm_bf16x3<<<ggrid, 256, GSMEM>>>(x, Wk, k);
    gemm_bf16x3<<<ggrid, 256, GSMEM>>>(x, Wv, v);

    // RoPE on q, k
    const int pairs = MTOT*D_MODEL/2;
    rope_kernel<<<(pairs + 255)/256, 256>>>(q, k);

    // Causal flash attention -> [B, S, D_MODEL]
    const int shmem = 4 * 64 * FPAD * (int)sizeof(float);   // 69632 B
    cudaFuncSetAttribute(flash_kernel, cudaFuncAttributeMaxDynamicSharedMemorySize, shmem);
    flash_kernel<<<dim3(SEQ/64, NHEADS, BATCH), 256, shmem>>>(q, k, v, att);

    // Output projection
    gemm_bf16x3<<<ggrid, 256, GSMEM>>>(att, Wo, out);
}

// round 6
// speedup vs baseline: 2.3502x; 1.5204x over previous
#include <cuda_runtime.h>
#include <cuda_bf16.h>
#include <math.h>
#include <stdint.h>

#define D_MODEL 1024
#define NHEADS  16
#define HDIM    64
#define BATCH   2
#define SEQ     2048
#define MTOT    (BATCH*SEQ)          // 4096
#define GK      1024

// Scratch (allocation-free rule: static __device__ globals)
__device__ float g_q[MTOT*D_MODEL];
__device__ float g_k[MTOT*D_MODEL];
__device__ float g_v[MTOT*D_MODEL];
__device__ float g_att[MTOT*D_MODEL];

// ===========================================================================
// helpers
// ===========================================================================
__device__ __forceinline__ uint32_t smem_u32(const void* p) {
    uint32_t a;
    asm("{ .reg .u64 t; cvta.to.shared.u64 t, %1; cvt.u32.u64 %0, t; }" : "=r"(a) : "l"(p));
    return a;
}

__device__ __forceinline__ void ldsm_x4(uint32_t* r, uint32_t addr) {
    asm volatile("ldmatrix.sync.aligned.m8n8.x4.shared.b16 {%0,%1,%2,%3}, [%4];"
        : "=r"(r[0]), "=r"(r[1]), "=r"(r[2]), "=r"(r[3]) : "r"(addr));
}
__device__ __forceinline__ void ldsm_x4_t(uint32_t* r, uint32_t addr) {
    asm volatile("ldmatrix.sync.aligned.m8n8.x4.trans.shared.b16 {%0,%1,%2,%3}, [%4];"
        : "=r"(r[0]), "=r"(r[1]), "=r"(r[2]), "=r"(r[3]) : "r"(addr));
}

__device__ __forceinline__ void mma_bf16(float* c, const uint32_t* a, uint32_t b0, uint32_t b1) {
    asm volatile("mma.sync.aligned.m16n8k16.row.col.f32.bf16.bf16.f32 "
        "{%0,%1,%2,%3}, {%4,%5,%6,%7}, {%8,%9}, {%0,%1,%2,%3};"
        : "+f"(c[0]), "+f"(c[1]), "+f"(c[2]), "+f"(c[3])
        : "r"(a[0]), "r"(a[1]), "r"(a[2]), "r"(a[3]), "r"(b0), "r"(b1));
}

__device__ __forceinline__ float ex2f(float x) {
    float y; asm("ex2.approx.f32 %0, %1;" : "=f"(y) : "f"(x)); return y;
}

// split 2 fp32 -> bf16 hi pair + bf16 lo pair (packed b32 each)
__device__ __forceinline__ void pack2(float x, float y, uint32_t& h, uint32_t& l) {
    __nv_bfloat162 hh = __floats2bfloat162_rn(x, y);
    float hx = __bfloat162float(hh.x), hy = __bfloat162float(hh.y);
    __nv_bfloat162 ll = __floats2bfloat162_rn(x - hx, y - hy);
    h = *(uint32_t*)&hh; l = *(uint32_t*)&ll;
}

// split 8 fp32 -> 8 bf16 hi + 8 bf16 lo, packed as uint4 each
__device__ __forceinline__ void split8(const float* f, uint4& h4, uint4& l4) {
    uint32_t hw[4], lw[4];
    #pragma unroll
    for (int j = 0; j < 4; j++) pack2(f[2*j], f[2*j+1], hw[j], lw[j]);
    h4 = make_uint4(hw[0], hw[1], hw[2], hw[3]);
    l4 = make_uint4(lw[0], lw[1], lw[2], lw[3]);
}

// ===========================================================================
// bf16x3 mma.sync GEMM (NT): C[m,n] = sum_k A[m,k]*W[n,k], fp32 in/out.
// 128x128 tile, BK=32, 256 thr (8 warps, 2x4), warp tile 64x32.
// ===========================================================================
#define BKK       32
#define NCHUNK    (GK/BKK)           // 32
#define TILE_B16  (128*32*2)         // 8192 bytes per bf16 tile
#define STAGE_B   (4*TILE_B16)       // Ah, Al, Bh, Bl = 32768
#define GSMEM     (2*STAGE_B)        // 65536 (double buffer)

__device__ __forceinline__ uint32_t sw_off(int row, int chunk) {
    return (uint32_t)(row*64 + ((chunk ^ ((row>>1)&3))<<4));
}

__global__ void __launch_bounds__(256) gemm_bf16x3(const float* __restrict__ A,
                                                   const float* __restrict__ W,
                                                   float* __restrict__ C)
{
    extern __shared__ char sm[];
    const int tid  = threadIdx.x;
    const int wid  = tid >> 5;
    const int lane = tid & 31;
    const int brow = blockIdx.y;
    const int bcol = blockIdx.x;

    const int wm = wid >> 2;          // 0..1 (m half)
    const int wn = wid & 3;           // 0..3 (n quarter)

    const int lrow = tid >> 1;
    const int lhalf = tid & 1;
    const float* Ag = A + (size_t)(brow*128 + lrow)*GK + lhalf*16;
    const float* Bg = W + (size_t)(bcol*128 + lrow)*GK + lhalf*16;
    const uint32_t so0 = sw_off(lrow, lhalf*2);
    const uint32_t so1 = sw_off(lrow, lhalf*2 + 1);

    const int l15 = lane & 15;
    const int l16 = lane >> 4;

    float acc[4][4][4];
    #pragma unroll
    for (int i = 0; i < 4; i++)
        #pragma unroll
        for (int j = 0; j < 4; j++)
            #pragma unroll
            for (int e = 0; e < 4; e++) acc[i][j][e] = 0.0f;

    float4 pa[4], pb[4];
    #pragma unroll
    for (int u = 0; u < 4; u++) {
        pa[u] = *(const float4*)(Ag + 4*u);
        pb[u] = *(const float4*)(Bg + 4*u);
    }

    for (int ch = 0; ch < NCHUNK; ch++) {
        char* stg = sm + (ch & 1)*STAGE_B;
        char* sAh = stg;
        char* sAl = stg + TILE_B16;
        char* sBh = stg + 2*TILE_B16;
        char* sBl = stg + 3*TILE_B16;

        {
            uint4 h4, l4;
            split8(&pa[0].x, h4, l4);
            *(uint4*)(sAh + so0) = h4; *(uint4*)(sAl + so0) = l4;
            split8(&pa[2].x, h4, l4);
            *(uint4*)(sAh + so1) = h4; *(uint4*)(sAl + so1) = l4;
            split8(&pb[0].x, h4, l4);
            *(uint4*)(sBh + so0) = h4; *(uint4*)(sBl + so0) = l4;
            split8(&pb[2].x, h4, l4);
            *(uint4*)(sBh + so1) = h4; *(uint4*)(sBl + so1) = l4;
        }
        __syncthreads();

        if (ch + 1 < NCHUNK) {
            #pragma unroll
            for (int u = 0; u < 4; u++) {
                pa[u] = *(const float4*)(Ag + (ch+1)*BKK + 4*u);
                pb[u] = *(const float4*)(Bg + (ch+1)*BKK + 4*u);
            }
        }

        const uint32_t uAh = smem_u32(sAh), uAl = smem_u32(sAl);
        const uint32_t uBh = smem_u32(sBh), uBl = smem_u32(sBl);

        #pragma unroll
        for (int s = 0; s < 2; s++) {
            const int chunk = s*2 + l16;

            uint32_t bh[2][4], bl[2][4];
            #pragma unroll
            for (int ng = 0; ng < 2; ng++) {
                const int brow_l = wn*32 + ng*16 + l15;
                const uint32_t off = sw_off(brow_l, chunk);
                ldsm_x4(bh[ng], uBh + off);
                ldsm_x4(bl[ng], uBl + off);
            }

            #pragma unroll
            for (int mt = 0; mt < 4; mt++) {
                const int arow_l = wm*64 + mt*16 + l15;
                const uint32_t off = sw_off(arow_l, chunk);
                uint32_t ah[4], al[4];
                ldsm_x4(ah, uAh + off);
                ldsm_x4(al, uAl + off);

                #pragma unroll
                for (int nt = 0; nt < 4; nt++) {
                    const int ng = nt >> 1, ix = nt & 1;
                    const uint32_t b0h = bh[ng][ix], b1h = bh[ng][2+ix];
                    const uint32_t b0l = bl[ng][ix], b1l = bl[ng][2+ix];
                    mma_bf16(acc[mt][nt], ah, b0h, b1h);
                    mma_bf16(acc[mt][nt], al, b0h, b1h);
                    mma_bf16(acc[mt][nt], ah, b0l, b1l);
                }
            }
        }
        __syncthreads();
    }

    const int rbase = brow*128 + wm*64 + (lane >> 2);
    const int cbase = bcol*128 + wn*32 + (lane & 3)*2;
    #pragma unroll
    for (int mt = 0; mt < 4; mt++) {
        #pragma unroll
        for (int nt = 0; nt < 4; nt++) {
            float* p = C + (size_t)(rbase + mt*16)*D_MODEL + cbase + nt*8;
            *(float2*)p = make_float2(acc[mt][nt][0], acc[mt][nt][1]);
            *(float2*)(p + 8*D_MODEL) = make_float2(acc[mt][nt][2], acc[mt][nt][3]);
        }
    }
}

// ---------------------------------------------------------------------------
// RoPE in-place on q and k in [B, S, H, d] layout (interleaved pairs).
// ---------------------------------------------------------------------------
__global__ void rope_kernel(float* __restrict__ q, float* __restrict__ k)
{
    const int total = MTOT*D_MODEL/2;
    int i = blockIdx.x*blockDim.x + threadIdx.x;
    if (i >= total) return;

    const int t = i & 31;
    const int s = (i >> 9) & (SEQ - 1);
    const size_t base = (size_t)i * 2;

    const float ang = (float)s * exp2f((float)t * (-2.0f/(float)HDIM) * 13.28771237954945f);
    float sn, cs;
    sincosf(ang, &sn, &cs);

    float2 qv = *(float2*)(q + base);
    float2 kv = *(float2*)(k + base);
    float2 qo, ko;
    qo.x = qv.x*cs - qv.y*sn;  qo.y = qv.x*sn + qv.y*cs;
    ko.x = kv.x*cs - kv.y*sn;  ko.y = kv.x*sn + kv.y*cs;
    *(float2*)(q + base) = qo;
    *(float2*)(k + base) = ko;
}

// ===========================================================================
// Flash attention (causal) with mma.sync bf16x3 for QK^T and PV.
// CTA: 128 q-rows, 8 warps (m16 each), K/V tiles of 64 rows.
// Q pre-scaled by 0.125*log2(e); softmax in ex2 domain.
// Smem tiles: bf16 [rows][64 cols] = 128B rows, chunk swizzle c^(r&7).
// ===========================================================================
#define FSMEM 65536
// offsets: Qh 0, Ql 16K, Kh 32K, Kl 40K, Vh 48K, Vl 56K
#define FQH 0
#define FQL 16384
#define FKH 32768
#define FKL 40960
#define FVH 49152
#define FVL 57344
#define QSCL 0.18033688011112042f   // 0.125 * log2(e)

__device__ __forceinline__ uint32_t fsw(int row, int chunk) {
    return (uint32_t)(row*128 + ((chunk ^ (row & 7)) << 4));
}

__global__ void __launch_bounds__(256) flash_mma(const float* __restrict__ gq,
                                                 const float* __restrict__ gk,
                                                 const float* __restrict__ gv,
                                                 float* __restrict__ out)
{
    extern __shared__ char smc[];
    const int tid  = threadIdx.x;
    const int wid  = tid >> 5;
    const int lane = tid & 31;
    const int qt0  = blockIdx.x * 128;
    const int h    = blockIdx.y;
    const int b    = blockIdx.z;

    const float* Qg = gq + ((size_t)(b*SEQ + qt0))*D_MODEL + h*HDIM;
    const float* Kg = gk + ((size_t)(b*SEQ))*D_MODEL + h*HDIM;
    const float* Vg = gv + ((size_t)(b*SEQ))*D_MODEL + h*HDIM;

    // ---- load Q tile (128x64), scale, split, store swizzled ----
    {
        const int r = tid >> 1;
        const int ch0 = (tid & 1)*4;
        const float* src = Qg + (size_t)r*D_MODEL + (tid & 1)*32;
        #pragma unroll
        for (int u = 0; u < 4; u++) {
            float f[8];
            float4 a = *(const float4*)(src + 8*u);
            float4 c = *(const float4*)(src + 8*u + 4);
            f[0]=a.x*QSCL; f[1]=a.y*QSCL; f[2]=a.z*QSCL; f[3]=a.w*QSCL;
            f[4]=c.x*QSCL; f[5]=c.y*QSCL; f[6]=c.z*QSCL; f[7]=c.w*QSCL;
            uint4 h4, l4;
            split8(f, h4, l4);
            const uint32_t off = fsw(r, ch0 + u);
            *(uint4*)(smc + FQH + off) = h4;
            *(uint4*)(smc + FQL + off) = l4;
        }
    }
    __syncthreads();

    // ---- Q fragments (held in registers for whole kernel) ----
    uint32_t qh[4][4], ql[4][4];
    {
        const uint32_t uQh = smem_u32(smc + FQH), uQl = smem_u32(smc + FQL);
        const int r = wid*16 + (lane & 15);
        #pragma unroll
        for (int i = 0; i < 4; i++) {
            const uint32_t off = fsw(r, 2*i + (lane >> 4));
            ldsm_x4(qh[i], uQh + off);
            ldsm_x4(ql[i], uQl + off);
        }
    }

    float o[8][4];
    #pragma unroll
    for (int j = 0; j < 8; j++)
        #pragma unroll
        for (int e = 0; e < 4; e++) o[j][e] = 0.0f;
    float mrow[2] = {-INFINITY, -INFINITY};
    float lrow[2] = {0.0f, 0.0f};

    const uint32_t uKh = smem_u32(smc + FKH), uKl = smem_u32(smc + FKL);
    const uint32_t uVh = smem_u32(smc + FVH), uVl = smem_u32(smc + FVL);

    const int nkt = blockIdx.x*2 + 2;
    for (int kt = 0; kt < nkt; kt++) {
        __syncthreads();   // previous tile's V reads done
        // ---- load K,V tile (64x64 each), split, store swizzled ----
        {
            const int r  = tid >> 2;
            const int c0 = (tid & 3)*16;
            const float* ks = Kg + (size_t)(kt*64 + r)*D_MODEL + c0;
            const float* vs = Vg + (size_t)(kt*64 + r)*D_MODEL + c0;
            #pragma unroll
            for (int u = 0; u < 2; u++) {
                const uint32_t off = fsw(r, (c0 >> 3) + u);
                float f[8];
                float4 a = *(const float4*)(ks + 8*u);
                float4 c = *(const float4*)(ks + 8*u + 4);
                f[0]=a.x; f[1]=a.y; f[2]=a.z; f[3]=a.w;
                f[4]=c.x; f[5]=c.y; f[6]=c.z; f[7]=c.w;
                uint4 h4, l4;
                split8(f, h4, l4);
                *(uint4*)(smc + FKH + off) = h4;
                *(uint4*)(smc + FKL + off) = l4;
                a = *(const float4*)(vs + 8*u);
                c = *(const float4*)(vs + 8*u + 4);
                f[0]=a.x; f[1]=a.y; f[2]=a.z; f[3]=a.w;
                f[4]=c.x; f[5]=c.y; f[6]=c.z; f[7]=c.w;
                split8(f, h4, l4);
                *(uint4*)(smc + FVH + off) = h4;
                *(uint4*)(smc + FVL + off) = l4;
            }
        }
        __syncthreads();

        // warps whose rows are entirely above this K tile skip compute
        if (kt*64 > qt0 + wid*16 + 15) continue;

        // ---- S = Q K^T (bf16x3) ----
        float s[8][4];
        #pragma unroll
        for (int j = 0; j < 8; j++)
            #pragma unroll
            for (int e = 0; e < 4; e++) s[j][e] = 0.0f;

        #pragma unroll
        for (int i = 0; i < 4; i++) {
            uint32_t bh[4][4], bl[4][4];
            #pragma unroll
            for (int ng = 0; ng < 4; ng++) {
                const int r = ng*16 + (lane & 15);
                const uint32_t off = fsw(r, 2*i + (lane >> 4));
                ldsm_x4(bh[ng], uKh + off);
                ldsm_x4(bl[ng], uKl + off);
            }
            #pragma unroll
            for (int j = 0; j < 8; j++) {
                const int ng = j >> 1, ix = j & 1;
                const uint32_t b0h = bh[ng][ix], b1h = bh[ng][2+ix];
                const uint32_t b0l = bl[ng][ix], b1l = bl[ng][2+ix];
                mma_bf16(s[j], qh[i], b0h, b1h);
                mma_bf16(s[j], ql[i], b0h, b1h);
                mma_bf16(s[j], qh[i], b0l, b1l);
            }
        }

        // ---- causal mask (only near-diagonal tiles) ----
        if (kt*64 + 63 > qt0 + wid*16) {
            const int qr = qt0 + wid*16 + (lane >> 2);
            const int kc = kt*64 + (lane & 3)*2;
            #pragma unroll
            for (int j = 0; j < 8; j++) {
                #pragma unroll
                for (int e = 0; e < 4; e++) {
                    const int col = kc + j*8 + (e & 1);
                    const int row = qr + (e >> 1)*8;
                    if (col > row) s[j][e] = -INFINITY;
                }
            }
        }

        // ---- online softmax (ex2 domain) ----
        #pragma unroll
        for (int hf = 0; hf < 2; hf++) {
            float mx = -INFINITY;
            #pragma unroll
            for (int j = 0; j < 8; j++)
                mx = fmaxf(mx, fmaxf(s[j][2*hf], s[j][2*hf+1]));
            mx = fmaxf(mx, __shfl_xor_sync(0xffffffffu, mx, 1));
            mx = fmaxf(mx, __shfl_xor_sync(0xffffffffu, mx, 2));
            const float mn    = fmaxf(mrow[hf], mx);
            const float alpha = ex2f(mrow[hf] - mn);
            mrow[hf] = mn;
            float sum = 0.0f;
            #pragma unroll
            for (int j = 0; j < 8; j++) {
                const float p0 = ex2f(s[j][2*hf]   - mn);
                const float p1 = ex2f(s[j][2*hf+1] - mn);
                s[j][2*hf] = p0; s[j][2*hf+1] = p1;
                sum += p0 + p1;
            }
            sum += __shfl_xor_sync(0xffffffffu, sum, 1);
            sum += __shfl_xor_sync(0xffffffffu, sum, 2);
            lrow[hf] = lrow[hf]*alpha + sum;
            #pragma unroll
            for (int j = 0; j < 8; j++) {
                o[j][2*hf]   *= alpha;
                o[j][2*hf+1] *= alpha;
            }
        }

        // ---- pack P to bf16 hi/lo A-fragments ----
        uint32_t ph[4][4], pl[4][4];
        #pragma unroll
        for (int g = 0; g < 4; g++) {
            pack2(s[2*g][0],   s[2*g][1],   ph[g][0], pl[g][0]);
            pack2(s[2*g][2],   s[2*g][3],   ph[g][1], pl[g][1]);
            pack2(s[2*g+1][0], s[2*g+1][1], ph[g][2], pl[g][2]);
            pack2(s[2*g+1][2], s[2*g+1][3], ph[g][3], pl[g][3]);
        }

        // ---- O += P V (bf16x3, V via ldmatrix.trans) ----
        #pragma unroll
        for (int g = 0; g < 4; g++) {
            uint32_t vh[4][4], vl[4][4];
            #pragma unroll
            for (int ng = 0; ng < 4; ng++) {
                const int r = g*16 + (lane & 15);
                const uint32_t off = fsw(r, 2*ng + (lane >> 4));
                ldsm_x4_t(vh[ng], uVh + off);
                ldsm_x4_t(vl[ng], uVl + off);
            }
            #pragma unroll
            for (int j = 0; j < 8; j++) {
                const int ng = j >> 1, ix = j & 1;
                const uint32_t b0h = vh[ng][2*ix], b1h = vh[ng][2*ix+1];
                const uint32_t b0l = vl[ng][2*ix], b1l = vl[ng][2*ix+1];
                mma_bf16(o[j], ph[g], b0h, b1h);
                mma_bf16(o[j], pl[g], b0h, b1h);
                mma_bf16(o[j], ph[g], b0l, b1l);
            }
        }
    }

    // ---- epilogue: normalize, write fp32 [B, S, D_MODEL] ----
    #pragma unroll
    for (int hf = 0; hf < 2; hf++) {
        const float inv = 1.0f / lrow[hf];
        const int row = qt0 + wid*16 + (lane >> 2) + hf*8;
        float* dst = out + ((size_t)(b*SEQ + row))*D_MODEL + h*HDIM + (lane & 3)*2;
        #pragma unroll
        for (int j = 0; j < 8; j++)
            *(float2*)(dst + j*8) = make_float2(o[j][2*hf]*inv, o[j][2*hf+1]*inv);
    }
}

// ---------------------------------------------------------------------------
extern "C" void kernel_launch(void* const* d_in, const int* in_sizes, int n_in,
                              void* d_out, int out_size)
{
    (void)in_sizes; (void)n_in; (void)out_size;
    const float* x  = (const float*)d_in[0];
    const float* Wq = (const float*)d_in[1];
    const float* Wk = (const float*)d_in[2];
    const float* Wv = (const float*)d_in[3];
    const float* Wo = (const float*)d_in[4];
    float* out = (float*)d_out;

    float *q, *k, *v, *att;
    cudaGetSymbolAddress((void**)&q,   g_q);
    cudaGetSymbolAddress((void**)&k,   g_k);
    cudaGetSymbolAddress((void**)&v,   g_v);
    cudaGetSymbolAddress((void**)&att, g_att);

    cudaFuncSetAttribute(gemm_bf16x3, cudaFuncAttributeMaxDynamicSharedMemorySize, GSMEM);
    cudaFuncSetAttribute(flash_mma,   cudaFuncAttributeMaxDynamicSharedMemorySize, FSMEM);

    dim3 ggrid(D_MODEL/128, MTOT/128);   // (8, 32) = 256 CTAs

    // QKV projections -> [B, S, H, d] (row-major [MTOT, D_MODEL])
    gemm_bf16x3<<<ggrid, 256, GSMEM>>>(x, Wq, q);
    gemm_bf16x3<<<ggrid, 256, GSMEM>>>(x, Wk, k);
    gemm_bf16x3<<<ggrid, 256, GSMEM>>>(x, Wv, v);

    // RoPE on q, k
    const int pairs = MTOT*D_MODEL/2;
    rope_kernel<<<(pairs + 255)/256, 256>>>(q, k);

    // Causal flash attention (tensor cores) -> [B, S, D_MODEL]
    flash_mma<<<dim3(SEQ/128, NHEADS, BATCH), 256, FSMEM>>>(q, k, v, att);

    // Output projection
    gemm_bf16x3<<<ggrid, 256, GSMEM>>>(att, Wo, out);
}

// round 9
// speedup vs baseline: 2.5479x; 1.0841x over previous
#include <cuda_runtime.h>
#include <cuda_bf16.h>
#include <math.h>
#include <stdint.h>

#define D_MODEL 1024
#define NHEADS  16
#define HDIM    64
#define BATCH   2
#define SEQ     2048
#define MTOT    (BATCH*SEQ)          // 4096
#define GK      1024
#define NELEM   (MTOT*D_MODEL)       // 4M
#define WELEM   (D_MODEL*D_MODEL)    // 1M

// Scratch (allocation-free rule: static __device__ globals)
__device__ float g_q[NELEM];
__device__ float g_k[NELEM];
__device__ float g_v[NELEM];
__device__ __nv_bfloat16 g_xh[NELEM],  g_xl[NELEM];
__device__ __nv_bfloat16 g_wqh[WELEM], g_wql[WELEM];
__device__ __nv_bfloat16 g_wkh[WELEM], g_wkl[WELEM];
__device__ __nv_bfloat16 g_wvh[WELEM], g_wvl[WELEM];
__device__ __nv_bfloat16 g_woh[WELEM], g_wol[WELEM];
__device__ __nv_bfloat16 g_qh[NELEM],  g_ql[NELEM];
__device__ __nv_bfloat16 g_kh[NELEM],  g_kl[NELEM];
__device__ __nv_bfloat16 g_vh[NELEM],  g_vl[NELEM];
__device__ __nv_bfloat16 g_ath[NELEM], g_atl[NELEM];

// ===========================================================================
// helpers
// ===========================================================================
__device__ __forceinline__ uint32_t smem_u32(const void* p) {
    uint32_t a;
    asm("{ .reg .u64 t; cvta.to.shared.u64 t, %1; cvt.u32.u64 %0, t; }" : "=r"(a) : "l"(p));
    return a;
}
__device__ __forceinline__ void ldsm_x4(uint32_t* r, uint32_t addr) {
    asm volatile("ldmatrix.sync.aligned.m8n8.x4.shared.b16 {%0,%1,%2,%3}, [%4];"
        : "=r"(r[0]), "=r"(r[1]), "=r"(r[2]), "=r"(r[3]) : "r"(addr));
}
__device__ __forceinline__ void ldsm_x4_t(uint32_t* r, uint32_t addr) {
    asm volatile("ldmatrix.sync.aligned.m8n8.x4.trans.shared.b16 {%0,%1,%2,%3}, [%4];"
        : "=r"(r[0]), "=r"(r[1]), "=r"(r[2]), "=r"(r[3]) : "r"(addr));
}
__device__ __forceinline__ void mma_bf16(float* c, const uint32_t* a, uint32_t b0, uint32_t b1) {
    asm volatile("mma.sync.aligned.m16n8k16.row.col.f32.bf16.bf16.f32 "
        "{%0,%1,%2,%3}, {%4,%5,%6,%7}, {%8,%9}, {%0,%1,%2,%3};"
        : "+f"(c[0]), "+f"(c[1]), "+f"(c[2]), "+f"(c[3])
        : "r"(a[0]), "r"(a[1]), "r"(a[2]), "r"(a[3]), "r"(b0), "r"(b1));
}
__device__ __forceinline__ float ex2f(float x) {
    float y; asm("ex2.approx.f32 %0, %1;" : "=f"(y) : "f"(x)); return y;
}
__device__ __forceinline__ void pack2(float x, float y, uint32_t& h, uint32_t& l) {
    __nv_bfloat162 hh = __floats2bfloat162_rn(x, y);
    float hx = __bfloat162float(hh.x), hy = __bfloat162float(hh.y);
    __nv_bfloat162 ll = __floats2bfloat162_rn(x - hx, y - hy);
    h = *(uint32_t*)&hh; l = *(uint32_t*)&ll;
}

#define CP16(dst, src) \
    asm volatile("cp.async.cg.shared.global [%0], [%1], 16;" :: "r"(dst), "l"(src) : "memory")
#define CPCOMMIT() asm volatile("cp.async.commit_group;" ::: "memory")
#define CPWAIT0()  asm volatile("cp.async.wait_group 0;" ::: "memory")

// ===========================================================================
// split kernel: fp32 -> bf16 hi/lo (pairwise)
// ===========================================================================
__global__ void split_kernel(const float* __restrict__ src,
                             __nv_bfloat16* __restrict__ hi,
                             __nv_bfloat16* __restrict__ lo, int n2)
{
    int i = blockIdx.x*blockDim.x + threadIdx.x;
    if (i >= n2) return;
    float2 v = *(const float2*)(src + 2*(size_t)i);
    uint32_t h, l;
    pack2(v.x, v.y, h, l);
    ((uint32_t*)hi)[i] = h;
    ((uint32_t*)lo)[i] = l;
}

// ===========================================================================
// rope + split: q (scaled by 0.125*log2e), k, v -> bf16 hi/lo arrays
// layout [B,S,H,d], pair index i: t=i&31, s=(i>>9)&2047
// ===========================================================================
#define QSCL 0.18033688011112042f   // 0.125 * log2(e)

__global__ void rope_split(const float* __restrict__ q, const float* __restrict__ k,
                           const float* __restrict__ v,
                           __nv_bfloat16* __restrict__ qh, __nv_bfloat16* __restrict__ ql,
                           __nv_bfloat16* __restrict__ kh, __nv_bfloat16* __restrict__ kl,
                           __nv_bfloat16* __restrict__ vh, __nv_bfloat16* __restrict__ vl)
{
    const int total = NELEM/2;
    int i = blockIdx.x*blockDim.x + threadIdx.x;
    if (i >= total) return;

    const int t = i & 31;
    const int s = (i >> 9) & (SEQ - 1);
    const size_t base = (size_t)i * 2;

    const float ang = (float)s * exp2f((float)t * (-2.0f/(float)HDIM) * 13.28771237954945f);
    float sn, cs;
    sincosf(ang, &sn, &cs);

    uint32_t h, l;
    float2 qv = *(const float2*)(q + base);
    pack2((qv.x*cs - qv.y*sn)*QSCL, (qv.x*sn + qv.y*cs)*QSCL, h, l);
    ((uint32_t*)qh)[i] = h; ((uint32_t*)ql)[i] = l;

    float2 kv = *(const float2*)(k + base);
    pack2(kv.x*cs - kv.y*sn, kv.x*sn + kv.y*cs, h, l);
    ((uint32_t*)kh)[i] = h; ((uint32_t*)kl)[i] = l;

    float2 vv = *(const float2*)(v + base);
    pack2(vv.x, vv.y, h, l);
    ((uint32_t*)vh)[i] = h; ((uint32_t*)vl)[i] = l;
}

// ===========================================================================
// bf16x3 mma.sync GEMM (NT) on pre-split inputs, cp.async pipelined.
// C[m,n] = sum_k (Ah+Al)[m,k]*(Bh+Bl)[n,k], 3 passes (drop Al*Bl).
// 128x128 tile, BK=32, 256 thr (8 warps 2x4), warp tile 64x32.
// Stage: Ah@0, Al@8192, Bh@16384, Bl@24576 (each 128x32 bf16 swizzled).
// ===========================================================================
#define STAGE2 32768
#define GSMEM2 65536

__device__ __forceinline__ uint32_t sw_off(int row, int chunk) {
    return (uint32_t)(row*64 + ((chunk ^ ((row>>1)&3))<<4));
}

__global__ void __launch_bounds__(256) gemm_pre(const __nv_bfloat16* __restrict__ Ah,
                                                const __nv_bfloat16* __restrict__ Al,
                                                const __nv_bfloat16* __restrict__ Bh,
                                                const __nv_bfloat16* __restrict__ Bl,
                                                float* __restrict__ C)
{
    extern __shared__ char sm[];
    const uint32_t smb = smem_u32(sm);
    const int tid  = threadIdx.x;
    const int wid  = tid >> 5;
    const int lane = tid & 31;
    const int brow = blockIdx.y;
    const int bcol = blockIdx.x;
    const int wm = wid >> 2;
    const int wn = wid & 3;

    const int lrow  = tid >> 1;
    const int lhalf = tid & 1;
    const size_t aoff = (size_t)(brow*128 + lrow)*GK;
    const size_t boff = (size_t)(bcol*128 + lrow)*GK;
    uint32_t soff[2];
    soff[0] = sw_off(lrow, lhalf*2);
    soff[1] = sw_off(lrow, lhalf*2+1);

    const int l15 = lane & 15;
    const int l16 = lane >> 4;

    float acc[4][4][4];
    #pragma unroll
    for (int i = 0; i < 4; i++)
        #pragma unroll
        for (int j = 0; j < 4; j++)
            #pragma unroll
            for (int e = 0; e < 4; e++) acc[i][j][e] = 0.0f;

    // prologue: chunk 0 -> stage 0
    {
        const uint32_t s0 = smb;
        #pragma unroll
        for (int u = 0; u < 2; u++) {
            const int chunk = lhalf*2 + u;
            const size_t ke = (size_t)chunk*8;
            CP16(s0 + 0     + soff[u], Ah + aoff + ke);
            CP16(s0 + 8192  + soff[u], Al + aoff + ke);
            CP16(s0 + 16384 + soff[u], Bh + boff + ke);
            CP16(s0 + 24576 + soff[u], Bl + boff + ke);
        }
        CPCOMMIT();
    }

    for (int ch = 0; ch < 32; ch++) {
        CPWAIT0();
        __syncthreads();

        if (ch < 31) {
            const uint32_t s0 = smb + ((ch+1)&1)*STAGE2;
            #pragma unroll
            for (int u = 0; u < 2; u++) {
                const int chunk = lhalf*2 + u;
                const size_t ke = (size_t)(ch+1)*32 + chunk*8;
                CP16(s0 + 0     + soff[u], Ah + aoff + ke);
                CP16(s0 + 8192  + soff[u], Al + aoff + ke);
                CP16(s0 + 16384 + soff[u], Bh + boff + ke);
                CP16(s0 + 24576 + soff[u], Bl + boff + ke);
            }
            CPCOMMIT();
        }

        const uint32_t st  = smb + (ch&1)*STAGE2;
        const uint32_t uAh = st, uAl = st + 8192, uBh = st + 16384, uBl = st + 24576;

        #pragma unroll
        for (int s = 0; s < 2; s++) {
            const int chunk = s*2 + l16;

            uint32_t bh[2][4], bl[2][4];
            #pragma unroll
            for (int ng = 0; ng < 2; ng++) {
                const int br = wn*32 + ng*16 + l15;
                const uint32_t off = sw_off(br, chunk);
                ldsm_x4(bh[ng], uBh + off);
                ldsm_x4(bl[ng], uBl + off);
            }

            #pragma unroll
            for (int mt = 0; mt < 4; mt++) {
                const int ar = wm*64 + mt*16 + l15;
                const uint32_t off = sw_off(ar, chunk);
                uint32_t ah[4], al[4];
                ldsm_x4(ah, uAh + off);
                ldsm_x4(al, uAl + off);

                #pragma unroll
                for (int nt = 0; nt < 4; nt++) {
                    const int ng = nt >> 1, ix = nt & 1;
                    const uint32_t b0h = bh[ng][ix], b1h = bh[ng][2+ix];
                    const uint32_t b0l = bl[ng][ix], b1l = bl[ng][2+ix];
                    mma_bf16(acc[mt][nt], ah, b0h, b1h);
                    mma_bf16(acc[mt][nt], al, b0h, b1h);
                    mma_bf16(acc[mt][nt], ah, b0l, b1l);
                }
            }
        }
    }

    const int rbase = brow*128 + wm*64 + (lane >> 2);
    const int cbase = bcol*128 + wn*32 + (lane & 3)*2;
    #pragma unroll
    for (int mt = 0; mt < 4; mt++) {
        #pragma unroll
        for (int nt = 0; nt < 4; nt++) {
            float* p = C + (size_t)(rbase + mt*16)*D_MODEL + cbase + nt*8;
            *(float2*)p = make_float2(acc[mt][nt][0], acc[mt][nt][1]);
            *(float2*)(p + 8*D_MODEL) = make_float2(acc[mt][nt][2], acc[mt][nt][3]);
        }
    }
}

// ===========================================================================
// Flash attention (causal), bf16x3 mma, pre-split inputs, cp.async pipelined.
// CTA: 128 q-rows, 8 warps (m16 each), K/V tiles 64 rows, KV double-buffered.
// smem: KV stage0 [0,32K), stage1 [32K,64K) (kh/kl/vh/vl @ +0/8K/16K/24K);
//       Q hi [64K,80K), Q lo [80K,96K).
// Epilogue writes att hi/lo bf16 (for the final pre-split GEMM).
// ===========================================================================
#define FKVSTG 32768
#define FQH2   65536
#define FQL2   81920
#define FSMEM2 98304

__device__ __forceinline__ uint32_t fsw(int row, int chunk) {
    return (uint32_t)(row*128 + ((chunk ^ (row & 7)) << 4));
}

__global__ void __launch_bounds__(256) flash_mma(const __nv_bfloat16* __restrict__ qh_g,
                                                 const __nv_bfloat16* __restrict__ ql_g,
                                                 const __nv_bfloat16* __restrict__ kh_g,
                                                 const __nv_bfloat16* __restrict__ kl_g,
                                                 const __nv_bfloat16* __restrict__ vh_g,
                                                 const __nv_bfloat16* __restrict__ vl_g,
                                                 __nv_bfloat16* __restrict__ ath,
                                                 __nv_bfloat16* __restrict__ atl)
{
    extern __shared__ char smc[];
    const uint32_t smb = smem_u32(smc);
    const int tid  = threadIdx.x;
    const int wid  = tid >> 5;
    const int lane = tid & 31;
    const int qt0  = blockIdx.x * 128;
    const int h    = blockIdx.y;
    const int b    = blockIdx.z;
    const size_t hoff = (size_t)h*HDIM;
    const size_t srow = (size_t)b*SEQ;

    // ---- prologue: Q tile (group 1) + KV tile 0 (group 2) ----
    {
        const int r = tid >> 1;
        const int half = tid & 1;
        const size_t ge = (srow + qt0 + r)*D_MODEL + hoff;
        #pragma unroll
        for (int u = 0; u < 4; u++) {
            const int chunk = half*4 + u;
            const uint32_t off = fsw(r, chunk);
            CP16(smb + FQH2 + off, qh_g + ge + chunk*8);
            CP16(smb + FQL2 + off, ql_g + ge + chunk*8);
        }
        CPCOMMIT();
    }
    {
        const int r = tid >> 2;
        const int qd = tid & 3;
        const size_t ge = (srow + r)*D_MODEL + hoff;
        #pragma unroll
        for (int u = 0; u < 2; u++) {
            const int chunk = qd*2 + u;
            const uint32_t off = fsw(r, chunk);
            CP16(smb + 0     + off, kh_g + ge + chunk*8);
            CP16(smb + 8192  + off, kl_g + ge + chunk*8);
            CP16(smb + 16384 + off, vh_g + ge + chunk*8);
            CP16(smb + 24576 + off, vl_g + ge + chunk*8);
        }
        CPCOMMIT();
    }
    CPWAIT0();
    __syncthreads();

    // ---- Q fragments (registers, whole kernel) ----
    uint32_t qh[4][4], ql[4][4];
    {
        const int r = wid*16 + (lane & 15);
        #pragma unroll
        for (int i = 0; i < 4; i++) {
            const uint32_t off = fsw(r, 2*i + (lane >> 4));
            ldsm_x4(qh[i], smb + FQH2 + off);
            ldsm_x4(ql[i], smb + FQL2 + off);
        }
    }

    float o[8][4];
    #pragma unroll
    for (int j = 0; j < 8; j++)
        #pragma unroll
        for (int e = 0; e < 4; e++) o[j][e] = 0.0f;
    float mrow[2] = {-INFINITY, -INFINITY};
    float lrow[2] = {0.0f, 0.0f};

    const int nkt = blockIdx.x*2 + 2;
    for (int kt = 0; kt < nkt; kt++) {
        // issue next KV tile into other stage
        if (kt + 1 < nkt) {
            const uint32_t s0 = smb + ((kt+1)&1)*FKVSTG;
            const int r = tid >> 2;
            const int qd = tid & 3;
            const size_t ge = (srow + (kt+1)*64 + r)*D_MODEL + hoff;
            #pragma unroll
            for (int u = 0; u < 2; u++) {
                const int chunk = qd*2 + u;
                const uint32_t off = fsw(r, chunk);
                CP16(s0 + 0     + off, kh_g + ge + chunk*8);
                CP16(s0 + 8192  + off, kl_g + ge + chunk*8);
                CP16(s0 + 16384 + off, vh_g + ge + chunk*8);
                CP16(s0 + 24576 + off, vl_g + ge + chunk*8);
            }
            CPCOMMIT();
        }

        // warps whose rows are entirely above this K tile skip compute
        if (kt*64 <= qt0 + wid*16 + 15) {
            const uint32_t st  = smb + (kt&1)*FKVSTG;
            const uint32_t uKh = st, uKl = st + 8192, uVh = st + 16384, uVl = st + 24576;

            // ---- S = Q K^T (bf16x3) ----
            float s[8][4];
            #pragma unroll
            for (int j = 0; j < 8; j++)
                #pragma unroll
                for (int e = 0; e < 4; e++) s[j][e] = 0.0f;

            #pragma unroll
            for (int i = 0; i < 4; i++) {
                uint32_t bh[4][4], bl[4][4];
                #pragma unroll
                for (int ng = 0; ng < 4; ng++) {
                    const int r = ng*16 + (lane & 15);
                    const uint32_t off = fsw(r, 2*i + (lane >> 4));
                    ldsm_x4(bh[ng], uKh + off);
                    ldsm_x4(bl[ng], uKl + off);
                }
                #pragma unroll
                for (int j = 0; j < 8; j++) {
                    const int ng = j >> 1, ix = j & 1;
                    const uint32_t b0h = bh[ng][ix], b1h = bh[ng][2+ix];
                    const uint32_t b0l = bl[ng][ix], b1l = bl[ng][2+ix];
                    mma_bf16(s[j], qh[i], b0h, b1h);
                    mma_bf16(s[j], ql[i], b0h, b1h);
                    mma_bf16(s[j], qh[i], b0l, b1l);
                }
            }

            // ---- causal mask (near-diagonal tiles) ----
            if (kt*64 + 63 > qt0 + wid*16) {
                const int qr = qt0 + wid*16 + (lane >> 2);
                const int kc = kt*64 + (lane & 3)*2;
                #pragma unroll
                for (int j = 0; j < 8; j++) {
                    #pragma unroll
                    for (int e = 0; e < 4; e++) {
                        const int col = kc + j*8 + (e & 1);
                        const int row = qr + (e >> 1)*8;
                        if (col > row) s[j][e] = -INFINITY;
                    }
                }
            }

            // ---- online softmax (ex2 domain) ----
            #pragma unroll
            for (int hf = 0; hf < 2; hf++) {
                float mx = -INFINITY;
                #pragma unroll
                for (int j = 0; j < 8; j++)
                    mx = fmaxf(mx, fmaxf(s[j][2*hf], s[j][2*hf+1]));
                mx = fmaxf(mx, __shfl_xor_sync(0xffffffffu, mx, 1));
                mx = fmaxf(mx, __shfl_xor_sync(0xffffffffu, mx, 2));
                const float mn    = fmaxf(mrow[hf], mx);
                const float alpha = ex2f(mrow[hf] - mn);
                mrow[hf] = mn;
                float sum = 0.0f;
                #pragma unroll
                for (int j = 0; j < 8; j++) {
                    const float p0 = ex2f(s[j][2*hf]   - mn);
                    const float p1 = ex2f(s[j][2*hf+1] - mn);
                    s[j][2*hf] = p0; s[j][2*hf+1] = p1;
                    sum += p0 + p1;
                }
                sum += __shfl_xor_sync(0xffffffffu, sum, 1);
                sum += __shfl_xor_sync(0xffffffffu, sum, 2);
                lrow[hf] = lrow[hf]*alpha + sum;
                #pragma unroll
                for (int j = 0; j < 8; j++) {
                    o[j][2*hf]   *= alpha;
                    o[j][2*hf+1] *= alpha;
                }
            }

            // ---- pack P to bf16 hi/lo A-fragments ----
            uint32_t ph[4][4], pl[4][4];
            #pragma unroll
            for (int g = 0; g < 4; g++) {
                pack2(s[2*g][0],   s[2*g][1],   ph[g][0], pl[g][0]);
                pack2(s[2*g][2],   s[2*g][3],   ph[g][1], pl[g][1]);
                pack2(s[2*g+1][0], s[2*g+1][1], ph[g][2], pl[g][2]);
                pack2(s[2*g+1][2], s[2*g+1][3], ph[g][3], pl[g][3]);
            }

            // ---- O += P V (bf16x3, V via ldmatrix.trans) ----
            #pragma unroll
            for (int g = 0; g < 4; g++) {
                uint32_t vh[4][4], vl[4][4];
                #pragma unroll
                for (int ng = 0; ng < 4; ng++) {
                    const int r = g*16 + (lane & 15);
                    const uint32_t off = fsw(r, 2*ng + (lane >> 4));
                    ldsm_x4_t(vh[ng], uVh + off);
                    ldsm_x4_t(vl[ng], uVl + off);
                }
                #pragma unroll
                for (int j = 0; j < 8; j++) {
                    const int ng = j >> 1, ix = j & 1;
                    const uint32_t b0h = vh[ng][2*ix], b1h = vh[ng][2*ix+1];
                    const uint32_t b0l = vl[ng][2*ix], b1l = vl[ng][2*ix+1];
                    mma_bf16(o[j], ph[g], b0h, b1h);
                    mma_bf16(o[j], pl[g], b0h, b1h);
                    mma_bf16(o[j], ph[g], b0l, b1l);
                }
            }
        }

        CPWAIT0();
        __syncthreads();
    }

    // ---- epilogue: normalize, split, write bf16 hi/lo att ----
    #pragma unroll
    for (int hf = 0; hf < 2; hf++) {
        const float inv = 1.0f / lrow[hf];
        const int row = qt0 + wid*16 + (lane >> 2) + hf*8;
        const size_t ebase = (srow + row)*D_MODEL + hoff + (lane & 3)*2;
        #pragma unroll
        for (int j = 0; j < 8; j++) {
            uint32_t hw, lw;
            pack2(o[j][2*hf]*inv, o[j][2*hf+1]*inv, hw, lw);
            ((uint32_t*)ath)[(ebase + j*8) >> 1] = hw;
            ((uint32_t*)atl)[(ebase + j*8) >> 1] = lw;
        }
    }
}

// ---------------------------------------------------------------------------
extern "C" void kernel_launch(void* const* d_in, const int* in_sizes, int n_in,
                              void* d_out, int out_size)
{
    (void)in_sizes; (void)n_in; (void)out_size;
    const float* x  = (const float*)d_in[0];
    const float* Wq = (const float*)d_in[1];
    const float* Wk = (const float*)d_in[2];
    const float* Wv = (const float*)d_in[3];
    const float* Wo = (const float*)d_in[4];
    float* out = (float*)d_out;

    float *q, *k, *v;
    __nv_bfloat16 *xh, *xl, *wqh, *wql, *wkh, *wkl, *wvh, *wvl, *woh, *wol;
    __nv_bfloat16 *qh, *ql, *kh, *kl, *vh, *vl, *ath, *atl;
    cudaGetSymbolAddress((void**)&q,   g_q);
    cudaGetSymbolAddress((void**)&k,   g_k);
    cudaGetSymbolAddress((void**)&v,   g_v);
    cudaGetSymbolAddress((void**)&xh,  g_xh);  cudaGetSymbolAddress((void**)&xl,  g_xl);
    cudaGetSymbolAddress((void**)&wqh, g_wqh); cudaGetSymbolAddress((void**)&wql, g_wql);
    cudaGetSymbolAddress((void**)&wkh, g_wkh); cudaGetSymbolAddress((void**)&wkl, g_wkl);
    cudaGetSymbolAddress((void**)&wvh, g_wvh); cudaGetSymbolAddress((void**)&wvl, g_wvl);
    cudaGetSymbolAddress((void**)&woh, g_woh); cudaGetSymbolAddress((void**)&wol, g_wol);
    cudaGetSymbolAddress((void**)&qh,  g_qh);  cudaGetSymbolAddress((void**)&ql,  g_ql);
    cudaGetSymbolAddress((void**)&kh,  g_kh);  cudaGetSymbolAddress((void**)&kl,  g_kl);
    cudaGetSymbolAddress((void**)&vh,  g_vh);  cudaGetSymbolAddress((void**)&vl,  g_vl);
    cudaGetSymbolAddress((void**)&ath, g_ath); cudaGetSymbolAddress((void**)&atl, g_atl);

    cudaFuncSetAttribute(gemm_pre,  cudaFuncAttributeMaxDynamicSharedMemorySize, GSMEM2);
    cudaFuncSetAttribute(flash_mma, cudaFuncAttributeMaxDynamicSharedMemorySize, FSMEM2);

    // 1) split inputs to bf16 hi/lo
    split_kernel<<<(NELEM/2 + 255)/256, 256>>>(x,  xh,  xl,  NELEM/2);
    split_kernel<<<(WELEM/2 + 255)/256, 256>>>(Wq, wqh, wql, WELEM/2);
    split_kernel<<<(WELEM/2 + 255)/256, 256>>>(Wk, wkh, wkl, WELEM/2);
    split_kernel<<<(WELEM/2 + 255)/256, 256>>>(Wv, wvh, wvl, WELEM/2);
    split_kernel<<<(WELEM/2 + 255)/256, 256>>>(Wo, woh, wol, WELEM/2);

    // 2) QKV projections -> fp32 [B,S,H,d]
    dim3 ggrid(D_MODEL/128, MTOT/128);   // (8, 32)
    gemm_pre<<<ggrid, 256, GSMEM2>>>(xh, xl, wqh, wql, q);
    gemm_pre<<<ggrid, 256, GSMEM2>>>(xh, xl, wkh, wkl, k);
    gemm_pre<<<ggrid, 256, GSMEM2>>>(xh, xl, wvh, wvl, v);

    // 3) RoPE + split q/k/v -> bf16 hi/lo
    rope_split<<<(NELEM/2 + 255)/256, 256>>>(q, k, v, qh, ql, kh, kl, vh, vl);

    // 4) Causal flash attention -> att bf16 hi/lo
    flash_mma<<<dim3(SEQ/128, NHEADS, BATCH), 256, FSMEM2>>>(qh, ql, kh, kl, vh, vl, ath, atl);

    // 5) Output projection -> fp32 out
    gemm_pre<<<ggrid, 256, GSMEM2>>>(ath, atl, woh, wol, out);
}

// round 10
// speedup vs baseline: 2.6735x; 1.0493x over previous
#include <cuda_runtime.h>
#include <cuda_bf16.h>
#include <math.h>
#include <stdint.h>

#define D_MODEL 1024
#define NHEADS  16
#define HDIM    64
#define BATCH   2
#define SEQ     2048
#define MTOT    (BATCH*SEQ)          // 4096
#define GK      1024
#define NELEM   (MTOT*D_MODEL)       // 4M
#define WELEM   (D_MODEL*D_MODEL)    // 1M

// Scratch (allocation-free rule: static __device__ globals)
__device__ __nv_bfloat16 g_xh[NELEM],  g_xl[NELEM];
__device__ __nv_bfloat16 g_wqh[WELEM], g_wql[WELEM];
__device__ __nv_bfloat16 g_wkh[WELEM], g_wkl[WELEM];
__device__ __nv_bfloat16 g_wvh[WELEM], g_wvl[WELEM];
__device__ __nv_bfloat16 g_woh[WELEM], g_wol[WELEM];
__device__ __nv_bfloat16 g_qh[NELEM],  g_ql[NELEM];
__device__ __nv_bfloat16 g_kh[NELEM],  g_kl[NELEM];
__device__ __nv_bfloat16 g_vh[NELEM],  g_vl[NELEM];
__device__ __nv_bfloat16 g_ath[NELEM], g_atl[NELEM];
__device__ float2 g_trig[SEQ*(HDIM/2)];   // [s][t] -> (cos, sin)

// ===========================================================================
// helpers
// ===========================================================================
__device__ __forceinline__ uint32_t smem_u32(const void* p) {
    uint32_t a;
    asm("{ .reg .u64 t; cvta.to.shared.u64 t, %1; cvt.u32.u64 %0, t; }" : "=r"(a) : "l"(p));
    return a;
}
__device__ __forceinline__ void ldsm_x4(uint32_t* r, uint32_t addr) {
    asm volatile("ldmatrix.sync.aligned.m8n8.x4.shared.b16 {%0,%1,%2,%3}, [%4];"
        : "=r"(r[0]), "=r"(r[1]), "=r"(r[2]), "=r"(r[3]) : "r"(addr));
}
__device__ __forceinline__ void ldsm_x4_t(uint32_t* r, uint32_t addr) {
    asm volatile("ldmatrix.sync.aligned.m8n8.x4.trans.shared.b16 {%0,%1,%2,%3}, [%4];"
        : "=r"(r[0]), "=r"(r[1]), "=r"(r[2]), "=r"(r[3]) : "r"(addr));
}
__device__ __forceinline__ void mma_bf16(float* c, const uint32_t* a, uint32_t b0, uint32_t b1) {
    asm volatile("mma.sync.aligned.m16n8k16.row.col.f32.bf16.bf16.f32 "
        "{%0,%1,%2,%3}, {%4,%5,%6,%7}, {%8,%9}, {%0,%1,%2,%3};"
        : "+f"(c[0]), "+f"(c[1]), "+f"(c[2]), "+f"(c[3])
        : "r"(a[0]), "r"(a[1]), "r"(a[2]), "r"(a[3]), "r"(b0), "r"(b1));
}
__device__ __forceinline__ float ex2f(float x) {
    float y; asm("ex2.approx.f32 %0, %1;" : "=f"(y) : "f"(x)); return y;
}
__device__ __forceinline__ void pack2(float x, float y, uint32_t& h, uint32_t& l) {
    __nv_bfloat162 hh = __floats2bfloat162_rn(x, y);
    float hx = __bfloat162float(hh.x), hy = __bfloat162float(hh.y);
    __nv_bfloat162 ll = __floats2bfloat162_rn(x - hx, y - hy);
    h = *(uint32_t*)&hh; l = *(uint32_t*)&ll;
}

#define CP16(dst, src) \
    asm volatile("cp.async.cg.shared.global [%0], [%1], 16;" :: "r"(dst), "l"(src) : "memory")
#define CPCOMMIT() asm volatile("cp.async.commit_group;" ::: "memory")
#define CPWAIT0()  asm volatile("cp.async.wait_group 0;" ::: "memory")

#define QSCL 0.18033688011112042f   // 0.125 * log2(e)

// ===========================================================================
// trig table: [s][t] -> (cos, sin) of s * 10000^(-2t/64)
// ===========================================================================
__global__ void trig_kernel(float2* __restrict__ trig)
{
    int i = blockIdx.x*blockDim.x + threadIdx.x;
    if (i >= SEQ*(HDIM/2)) return;
    const int t = i & 31;
    const int s = i >> 5;
    const float ang = (float)s * exp2f((float)t * (-2.0f/(float)HDIM) * 13.28771237954945f);
    float sn, cs;
    sincosf(ang, &sn, &cs);
    trig[i] = make_float2(cs, sn);
}

// ===========================================================================
// split_all: fp32 -> bf16 hi/lo for x + 4 weights, one launch.
// pair index space: [0,2M) x; [2M,2.5M) Wq; ... each weight 0.5M pairs.
// ===========================================================================
#define XPAIRS (NELEM/2)
#define WPAIRS (WELEM/2)

__global__ void split_all(const float* __restrict__ x,
                          const float* __restrict__ Wq, const float* __restrict__ Wk,
                          const float* __restrict__ Wv, const float* __restrict__ Wo,
                          __nv_bfloat16* xh, __nv_bfloat16* xl,
                          __nv_bfloat16* wqh, __nv_bfloat16* wql,
                          __nv_bfloat16* wkh, __nv_bfloat16* wkl,
                          __nv_bfloat16* wvh, __nv_bfloat16* wvl,
                          __nv_bfloat16* woh, __nv_bfloat16* wol)
{
    int i = blockIdx.x*blockDim.x + threadIdx.x;
    const int total = XPAIRS + 4*WPAIRS;
    if (i >= total) return;

    const float* src; __nv_bfloat16 *hi, *lo; int j;
    if (i < XPAIRS)                { src = x;  hi = xh;  lo = xl;  j = i; }
    else if (i < XPAIRS+WPAIRS)    { src = Wq; hi = wqh; lo = wql; j = i - XPAIRS; }
    else if (i < XPAIRS+2*WPAIRS)  { src = Wk; hi = wkh; lo = wkl; j = i - XPAIRS - WPAIRS; }
    else if (i < XPAIRS+3*WPAIRS)  { src = Wv; hi = wvh; lo = wvl; j = i - XPAIRS - 2*WPAIRS; }
    else                           { src = Wo; hi = woh; lo = wol; j = i - XPAIRS - 3*WPAIRS; }

    float2 v = *(const float2*)(src + 2*(size_t)j);
    uint32_t h, l;
    pack2(v.x, v.y, h, l);
    ((uint32_t*)hi)[j] = h;
    ((uint32_t*)lo)[j] = l;
}

// ===========================================================================
// swizzles
// ===========================================================================
__device__ __forceinline__ uint32_t sw_off(int row, int chunk) {
    return (uint32_t)(row*64 + ((chunk ^ ((row>>1)&3))<<4));
}
__device__ __forceinline__ uint32_t fsw(int row, int chunk) {
    return (uint32_t)(row*128 + ((chunk ^ (row & 7)) << 4));
}

#define STAGE2 32768
#define GSMEM2 65536

// ===========================================================================
// GEMM mainloop shared by both GEMM kernels (acc += (Ah+Al)(Bh+Bl), 3 passes)
// ===========================================================================
__device__ __forceinline__ void gemm_mainloop(
    uint32_t smb, const __nv_bfloat16* Ah, const __nv_bfloat16* Al,
    const __nv_bfloat16* Bh, const __nv_bfloat16* Bl,
    size_t aoff, size_t boff, const uint32_t* soff,
    int lhalf, int wm, int wn, int l15, int l16, float acc[4][4][4])
{
    // prologue: chunk 0 -> stage 0
    {
        const uint32_t s0 = smb;
        #pragma unroll
        for (int u = 0; u < 2; u++) {
            const int chunk = lhalf*2 + u;
            const size_t ke = (size_t)chunk*8;
            CP16(s0 + 0     + soff[u], Ah + aoff + ke);
            CP16(s0 + 8192  + soff[u], Al + aoff + ke);
            CP16(s0 + 16384 + soff[u], Bh + boff + ke);
            CP16(s0 + 24576 + soff[u], Bl + boff + ke);
        }
        CPCOMMIT();
    }

    for (int ch = 0; ch < 32; ch++) {
        CPWAIT0();
        __syncthreads();

        if (ch < 31) {
            const uint32_t s0 = smb + ((ch+1)&1)*STAGE2;
            #pragma unroll
            for (int u = 0; u < 2; u++) {
                const int chunk = lhalf*2 + u;
                const size_t ke = (size_t)(ch+1)*32 + chunk*8;
                CP16(s0 + 0     + soff[u], Ah + aoff + ke);
                CP16(s0 + 8192  + soff[u], Al + aoff + ke);
                CP16(s0 + 16384 + soff[u], Bh + boff + ke);
                CP16(s0 + 24576 + soff[u], Bl + boff + ke);
            }
            CPCOMMIT();
        }

        const uint32_t st  = smb + (ch&1)*STAGE2;
        const uint32_t uAh = st, uAl = st + 8192, uBh = st + 16384, uBl = st + 24576;

        #pragma unroll
        for (int s = 0; s < 2; s++) {
            const int chunk = s*2 + l16;

            uint32_t bh[2][4], bl[2][4];
            #pragma unroll
            for (int ng = 0; ng < 2; ng++) {
                const int br = wn*32 + ng*16 + l15;
                const uint32_t off = sw_off(br, chunk);
                ldsm_x4(bh[ng], uBh + off);
                ldsm_x4(bl[ng], uBl + off);
            }

            #pragma unroll
            for (int mt = 0; mt < 4; mt++) {
                const int ar = wm*64 + mt*16 + l15;
                const uint32_t off = sw_off(ar, chunk);
                uint32_t ah[4], al[4];
                ldsm_x4(ah, uAh + off);
                ldsm_x4(al, uAl + off);

                #pragma unroll
                for (int nt = 0; nt < 4; nt++) {
                    const int ng = nt >> 1, ix = nt & 1;
                    const uint32_t b0h = bh[ng][ix], b1h = bh[ng][2+ix];
                    const uint32_t b0l = bl[ng][ix], b1l = bl[ng][2+ix];
                    mma_bf16(acc[mt][nt], ah, b0h, b1h);
                    mma_bf16(acc[mt][nt], al, b0h, b1h);
                    mma_bf16(acc[mt][nt], ah, b0l, b1l);
                }
            }
        }
    }
}

// ===========================================================================
// Fused QKV GEMM: grid (24, 32). bcol>>3 selects Wq/Wk/Wv; epilogue applies
// RoPE (q,k; q also scaled) via trig table and writes bf16 hi/lo directly.
// ===========================================================================
__global__ void __launch_bounds__(256) gemm_qkv(const __nv_bfloat16* __restrict__ xh,
                                                const __nv_bfloat16* __restrict__ xl,
                                                const __nv_bfloat16* __restrict__ wqh, const __nv_bfloat16* __restrict__ wql,
                                                const __nv_bfloat16* __restrict__ wkh, const __nv_bfloat16* __restrict__ wkl,
                                                const __nv_bfloat16* __restrict__ wvh, const __nv_bfloat16* __restrict__ wvl,
                                                __nv_bfloat16* __restrict__ qh_o, __nv_bfloat16* __restrict__ ql_o,
                                                __nv_bfloat16* __restrict__ kh_o, __nv_bfloat16* __restrict__ kl_o,
                                                __nv_bfloat16* __restrict__ vh_o, __nv_bfloat16* __restrict__ vl_o,
                                                const float2* __restrict__ trig)
{
    extern __shared__ char sm[];
    const uint32_t smb = smem_u32(sm);
    const int tid  = threadIdx.x;
    const int wid  = tid >> 5;
    const int lane = tid & 31;
    const int brow = blockIdx.y;
    const int bcol = blockIdx.x;
    const int sel  = bcol >> 3;          // 0=q, 1=k, 2=v
    const int bc   = bcol & 7;
    const int wm = wid >> 2;
    const int wn = wid & 3;

    const __nv_bfloat16* Bh = (sel == 0) ? wqh : (sel == 1) ? wkh : wvh;
    const __nv_bfloat16* Bl = (sel == 0) ? wql : (sel == 1) ? wkl : wvl;
    __nv_bfloat16* Oh = (sel == 0) ? qh_o : (sel == 1) ? kh_o : vh_o;
    __nv_bfloat16* Ol = (sel == 0) ? ql_o : (sel == 1) ? kl_o : vl_o;

    const int lrow  = tid >> 1;
    const int lhalf = tid & 1;
    const size_t aoff = (size_t)(brow*128 + lrow)*GK;
    const size_t boff = (size_t)(bc*128 + lrow)*GK;
    uint32_t soff[2];
    soff[0] = sw_off(lrow, lhalf*2);
    soff[1] = sw_off(lrow, lhalf*2+1);

    const int l15 = lane & 15;
    const int l16 = lane >> 4;

    float acc[4][4][4];
    #pragma unroll
    for (int i = 0; i < 4; i++)
        #pragma unroll
        for (int j = 0; j < 4; j++)
            #pragma unroll
            for (int e = 0; e < 4; e++) acc[i][j][e] = 0.0f;

    gemm_mainloop(smb, xh, xl, Bh, Bl, aoff, boff, soff, lhalf, wm, wn, l15, l16, acc);

    // epilogue: RoPE (sel<2) + split + bf16 store
    const int rbase = brow*128 + wm*64 + (lane >> 2);
    const int cb    = bc*128 + wn*32 + (lane & 3)*2;   // col in [0,1024), even
    #pragma unroll
    for (int mt = 0; mt < 4; mt++) {
        #pragma unroll
        for (int nt = 0; nt < 4; nt++) {
            const int col = cb + nt*8;
            const int t   = (col & 63) >> 1;
            #pragma unroll
            for (int half = 0; half < 2; half++) {
                const int row = rbase + mt*16 + half*8;
                float e = acc[mt][nt][2*half];
                float o = acc[mt][nt][2*half+1];
                if (sel < 2) {
                    const float2 cs = trig[(row & (SEQ-1))*32 + t];
                    float re = e*cs.x - o*cs.y;
                    float ro = e*cs.y + o*cs.x;
                    if (sel == 0) { re *= QSCL; ro *= QSCL; }
                    e = re; o = ro;
                }
                uint32_t hw, lw;
                pack2(e, o, hw, lw);
                const size_t idx = ((size_t)row*D_MODEL + col) >> 1;
                ((uint32_t*)Oh)[idx] = hw;
                ((uint32_t*)Ol)[idx] = lw;
            }
        }
    }
}

// ===========================================================================
// Output-projection GEMM (fp32 C), identical mainloop.
// ===========================================================================
__global__ void __launch_bounds__(256) gemm_pre(const __nv_bfloat16* __restrict__ Ah,
                                                const __nv_bfloat16* __restrict__ Al,
                                                const __nv_bfloat16* __restrict__ Bh,
                                                const __nv_bfloat16* __restrict__ Bl,
                                                float* __restrict__ C)
{
    extern __shared__ char sm[];
    const uint32_t smb = smem_u32(sm);
    const int tid  = threadIdx.x;
    const int wid  = tid >> 5;
    const int lane = tid & 31;
    const int brow = blockIdx.y;
    const int bcol = blockIdx.x;
    const int wm = wid >> 2;
    const int wn = wid & 3;

    const int lrow  = tid >> 1;
    const int lhalf = tid & 1;
    const size_t aoff = (size_t)(brow*128 + lrow)*GK;
    const size_t boff = (size_t)(bcol*128 + lrow)*GK;
    uint32_t soff[2];
    soff[0] = sw_off(lrow, lhalf*2);
    soff[1] = sw_off(lrow, lhalf*2+1);

    const int l15 = lane & 15;
    const int l16 = lane >> 4;

    float acc[4][4][4];
    #pragma unroll
    for (int i = 0; i < 4; i++)
        #pragma unroll
        for (int j = 0; j < 4; j++)
            #pragma unroll
            for (int e = 0; e < 4; e++) acc[i][j][e] = 0.0f;

    gemm_mainloop(smb, Ah, Al, Bh, Bl, aoff, boff, soff, lhalf, wm, wn, l15, l16, acc);

    const int rbase = brow*128 + wm*64 + (lane >> 2);
    const int cbase = bcol*128 + wn*32 + (lane & 3)*2;
    #pragma unroll
    for (int mt = 0; mt < 4; mt++) {
        #pragma unroll
        for (int nt = 0; nt < 4; nt++) {
            float* p = C + (size_t)(rbase + mt*16)*D_MODEL + cbase + nt*8;
            *(float2*)p = make_float2(acc[mt][nt][0], acc[mt][nt][1]);
            *(float2*)(p + 8*D_MODEL) = make_float2(acc[mt][nt][2], acc[mt][nt][3]);
        }
    }
}

// ===========================================================================
// Flash attention (causal), bf16x3 mma, pre-split inputs, cp.async pipelined.
// qtile REVERSED vs blockIdx.x so the largest causal CTAs launch first.
// ===========================================================================
#define FKVSTG 32768
#define FQH2   65536
#define FQL2   81920
#define FSMEM2 98304

__global__ void __launch_bounds__(256) flash_mma(const __nv_bfloat16* __restrict__ qh_g,
                                                 const __nv_bfloat16* __restrict__ ql_g,
                                                 const __nv_bfloat16* __restrict__ kh_g,
                                                 const __nv_bfloat16* __restrict__ kl_g,
                                                 const __nv_bfloat16* __restrict__ vh_g,
                                                 const __nv_bfloat16* __restrict__ vl_g,
                                                 __nv_bfloat16* __restrict__ ath,
                                                 __nv_bfloat16* __restrict__ atl)
{
    extern __shared__ char smc[];
    const uint32_t smb = smem_u32(smc);
    const int tid  = threadIdx.x;
    const int wid  = tid >> 5;
    const int lane = tid & 31;
    const int qtile = (int)gridDim.x - 1 - (int)blockIdx.x;   // big CTAs first
    const int qt0  = qtile * 128;
    const int h    = blockIdx.y;
    const int b    = blockIdx.z;
    const size_t hoff = (size_t)h*HDIM;
    const size_t srow = (size_t)b*SEQ;

    // ---- prologue: Q tile + KV tile 0 ----
    {
        const int r = tid >> 1;
        const int half = tid & 1;
        const size_t ge = (srow + qt0 + r)*D_MODEL + hoff;
        #pragma unroll
        for (int u = 0; u < 4; u++) {
            const int chunk = half*4 + u;
            const uint32_t off = fsw(r, chunk);
            CP16(smb + FQH2 + off, qh_g + ge + chunk*8);
            CP16(smb + FQL2 + off, ql_g + ge + chunk*8);
        }
        CPCOMMIT();
    }
    {
        const int r = tid >> 2;
        const int qd = tid & 3;
        const size_t ge = (srow + r)*D_MODEL + hoff;
        #pragma unroll
        for (int u = 0; u < 2; u++) {
            const int chunk = qd*2 + u;
            const uint32_t off = fsw(r, chunk);
            CP16(smb + 0     + off, kh_g + ge + chunk*8);
            CP16(smb + 8192  + off, kl_g + ge + chunk*8);
            CP16(smb + 16384 + off, vh_g + ge + chunk*8);
            CP16(smb + 24576 + off, vl_g + ge + chunk*8);
        }
        CPCOMMIT();
    }
    CPWAIT0();
    __syncthreads();

    // ---- Q fragments (registers, whole kernel) ----
    uint32_t qh[4][4], ql[4][4];
    {
        const int r = wid*16 + (lane & 15);
        #pragma unroll
        for (int i = 0; i < 4; i++) {
            const uint32_t off = fsw(r, 2*i + (lane >> 4));
            ldsm_x4(qh[i], smb + FQH2 + off);
            ldsm_x4(ql[i], smb + FQL2 + off);
        }
    }

    float o[8][4];
    #pragma unroll
    for (int j = 0; j < 8; j++)
        #pragma unroll
        for (int e = 0; e < 4; e++) o[j][e] = 0.0f;
    float mrow[2] = {-INFINITY, -INFINITY};
    float lrow[2] = {0.0f, 0.0f};

    const int nkt = qtile*2 + 2;
    for (int kt = 0; kt < nkt; kt++) {
        if (kt + 1 < nkt) {
            const uint32_t s0 = smb + ((kt+1)&1)*FKVSTG;
            const int r = tid >> 2;
            const int qd = tid & 3;
            const size_t ge = (srow + (kt+1)*64 + r)*D_MODEL + hoff;
            #pragma unroll
            for (int u = 0; u < 2; u++) {
                const int chunk = qd*2 + u;
                const uint32_t off = fsw(r, chunk);
                CP16(s0 + 0     + off, kh_g + ge + chunk*8);
                CP16(s0 + 8192  + off, kl_g + ge + chunk*8);
                CP16(s0 + 16384 + off, vh_g + ge + chunk*8);
                CP16(s0 + 24576 + off, vl_g + ge + chunk*8);
            }
            CPCOMMIT();
        }

        if (kt*64 <= qt0 + wid*16 + 15) {
            const uint32_t st  = smb + (kt&1)*FKVSTG;
            const uint32_t uKh = st, uKl = st + 8192, uVh = st + 16384, uVl = st + 24576;

            float s[8][4];
            #pragma unroll
            for (int j = 0; j < 8; j++)
                #pragma unroll
                for (int e = 0; e < 4; e++) s[j][e] = 0.0f;

            #pragma unroll
            for (int i = 0; i < 4; i++) {
                uint32_t bh[4][4], bl[4][4];
                #pragma unroll
                for (int ng = 0; ng < 4; ng++) {
                    const int r = ng*16 + (lane & 15);
                    const uint32_t off = fsw(r, 2*i + (lane >> 4));
                    ldsm_x4(bh[ng], uKh + off);
                    ldsm_x4(bl[ng], uKl + off);
                }
                #pragma unroll
                for (int j = 0; j < 8; j++) {
                    const int ng = j >> 1, ix = j & 1;
                    const uint32_t b0h = bh[ng][ix], b1h = bh[ng][2+ix];
                    const uint32_t b0l = bl[ng][ix], b1l = bl[ng][2+ix];
                    mma_bf16(s[j], qh[i], b0h, b1h);
                    mma_bf16(s[j], ql[i], b0h, b1h);
                    mma_bf16(s[j], qh[i], b0l, b1l);
                }
            }

            if (kt*64 + 63 > qt0 + wid*16) {
                const int qr = qt0 + wid*16 + (lane >> 2);
                const int kc = kt*64 + (lane & 3)*2;
                #pragma unroll
                for (int j = 0; j < 8; j++) {
                    #pragma unroll
                    for (int e = 0; e < 4; e++) {
                        const int col = kc + j*8 + (e & 1);
                        const int row = qr + (e >> 1)*8;
                        if (col > row) s[j][e] = -INFINITY;
                    }
                }
            }

            #pragma unroll
            for (int hf = 0; hf < 2; hf++) {
                float mx = -INFINITY;
                #pragma unroll
                for (int j = 0; j < 8; j++)
                    mx = fmaxf(mx, fmaxf(s[j][2*hf], s[j][2*hf+1]));
                mx = fmaxf(mx, __shfl_xor_sync(0xffffffffu, mx, 1));
                mx = fmaxf(mx, __shfl_xor_sync(0xffffffffu, mx, 2));
                const float mn    = fmaxf(mrow[hf], mx);
                const float alpha = ex2f(mrow[hf] - mn);
                mrow[hf] = mn;
                float sum = 0.0f;
                #pragma unroll
                for (int j = 0; j < 8; j++) {
                    const float p0 = ex2f(s[j][2*hf]   - mn);
                    const float p1 = ex2f(s[j][2*hf+1] - mn);
                    s[j][2*hf] = p0; s[j][2*hf+1] = p1;
                    sum += p0 + p1;
                }
                sum += __shfl_xor_sync(0xffffffffu, sum, 1);
                sum += __shfl_xor_sync(0xffffffffu, sum, 2);
                lrow[hf] = lrow[hf]*alpha + sum;
                #pragma unroll
                for (int j = 0; j < 8; j++) {
                    o[j][2*hf]   *= alpha;
                    o[j][2*hf+1] *= alpha;
                }
            }

            uint32_t ph[4][4], pl[4][4];
            #pragma unroll
            for (int g = 0; g < 4; g++) {
                pack2(s[2*g][0],   s[2*g][1],   ph[g][0], pl[g][0]);
                pack2(s[2*g][2],   s[2*g][3],   ph[g][1], pl[g][1]);
                pack2(s[2*g+1][0], s[2*g+1][1], ph[g][2], pl[g][2]);
                pack2(s[2*g+1][2], s[2*g+1][3], ph[g][3], pl[g][3]);
            }

            #pragma unroll
            for (int g = 0; g < 4; g++) {
                uint32_t vh[4][4], vl[4][4];
                #pragma unroll
                for (int ng = 0; ng < 4; ng++) {
                    const int r = g*16 + (lane & 15);
                    const uint32_t off = fsw(r, 2*ng + (lane >> 4));
                    ldsm_x4_t(vh[ng], uVh + off);
                    ldsm_x4_t(vl[ng], uVl + off);
                }
                #pragma unroll
                for (int j = 0; j < 8; j++) {
                    const int ng = j >> 1, ix = j & 1;
                    const uint32_t b0h = vh[ng][2*ix], b1h = vh[ng][2*ix+1];
                    const uint32_t b0l = vl[ng][2*ix], b1l = vl[ng][2*ix+1];
                    mma_bf16(o[j], ph[g], b0h, b1h);
                    mma_bf16(o[j], pl[g], b0h, b1h);
                    mma_bf16(o[j], ph[g], b0l, b1l);
                }
            }
        }

        CPWAIT0();
        __syncthreads();
    }

    // ---- epilogue: normalize, split, write bf16 hi/lo att ----
    #pragma unroll
    for (int hf = 0; hf < 2; hf++) {
        const float inv = 1.0f / lrow[hf];
        const int row = qt0 + wid*16 + (lane >> 2) + hf*8;
        const size_t ebase = (srow + row)*D_MODEL + hoff + (lane & 3)*2;
        #pragma unroll
        for (int j = 0; j < 8; j++) {
            uint32_t hw, lw;
            pack2(o[j][2*hf]*inv, o[j][2*hf+1]*inv, hw, lw);
            ((uint32_t*)ath)[(ebase + j*8) >> 1] = hw;
            ((uint32_t*)atl)[(ebase + j*8) >> 1] = lw;
        }
    }
}

// ---------------------------------------------------------------------------
extern "C" void kernel_launch(void* const* d_in, const int* in_sizes, int n_in,
                              void* d_out, int out_size)
{
    (void)in_sizes; (void)n_in; (void)out_size;
    const float* x  = (const float*)d_in[0];
    const float* Wq = (const float*)d_in[1];
    const float* Wk = (const float*)d_in[2];
    const float* Wv = (const float*)d_in[3];
    const float* Wo = (const float*)d_in[4];
    float* out = (float*)d_out;

    __nv_bfloat16 *xh, *xl, *wqh, *wql, *wkh, *wkl, *wvh, *wvl, *woh, *wol;
    __nv_bfloat16 *qh, *ql, *kh, *kl, *vh, *vl, *ath, *atl;
    float2* trig;
    cudaGetSymbolAddress((void**)&xh,  g_xh);  cudaGetSymbolAddress((void**)&xl,  g_xl);
    cudaGetSymbolAddress((void**)&wqh, g_wqh); cudaGetSymbolAddress((void**)&wql, g_wql);
    cudaGetSymbolAddress((void**)&wkh, g_wkh); cudaGetSymbolAddress((void**)&wkl, g_wkl);
    cudaGetSymbolAddress((void**)&wvh, g_wvh); cudaGetSymbolAddress((void**)&wvl, g_wvl);
    cudaGetSymbolAddress((void**)&woh, g_woh); cudaGetSymbolAddress((void**)&wol, g_wol);
    cudaGetSymbolAddress((void**)&qh,  g_qh);  cudaGetSymbolAddress((void**)&ql,  g_ql);
    cudaGetSymbolAddress((void**)&kh,  g_kh);  cudaGetSymbolAddress((void**)&kl,  g_kl);
    cudaGetSymbolAddress((void**)&vh,  g_vh);  cudaGetSymbolAddress((void**)&vl,  g_vl);
    cudaGetSymbolAddress((void**)&ath, g_ath); cudaGetSymbolAddress((void**)&atl, g_atl);
    cudaGetSymbolAddress((void**)&trig, g_trig);

    cudaFuncSetAttribute(gemm_qkv,  cudaFuncAttributeMaxDynamicSharedMemorySize, GSMEM2);
    cudaFuncSetAttribute(gemm_pre,  cudaFuncAttributeMaxDynamicSharedMemorySize, GSMEM2);
    cudaFuncSetAttribute(flash_mma, cudaFuncAttributeMaxDynamicSharedMemorySize, FSMEM2);

    // 1) trig table + split inputs/weights to bf16 hi/lo
    trig_kernel<<<(SEQ*(HDIM/2) + 255)/256, 256>>>(trig);
    const int tot_pairs = XPAIRS + 4*WPAIRS;
    split_all<<<(tot_pairs + 255)/256, 256>>>(x, Wq, Wk, Wv, Wo,
                                              xh, xl, wqh, wql, wkh, wkl,
                                              wvh, wvl, woh, wol);

    // 2) Fused QKV projections + RoPE + split -> bf16 hi/lo q/k/v
    gemm_qkv<<<dim3(24, MTOT/128), 256, GSMEM2>>>(xh, xl, wqh, wql, wkh, wkl, wvh, wvl,
                                                  qh, ql, kh, kl, vh, vl, trig);

    // 3) Causal flash attention -> att bf16 hi/lo
    flash_mma<<<dim3(SEQ/128, NHEADS, BATCH), 256, FSMEM2>>>(qh, ql, kh, kl, vh, vl, ath, atl);

    // 4) Output projection -> fp32 out
    gemm_pre<<<dim3(D_MODEL/128, MTOT/128), 256, GSMEM2>>>(ath, atl, woh, wol, out);
}